// round 2
// baseline (speedup 1.0000x reference)
#include <cuda_runtime.h>
#include <math.h>

#define NB 4096

// ----- scratch (device globals; no allocations) -----
__device__ float  g_h1[NB * 32 * 196];
__device__ float  g_out2[NB * 64 * 196];
__device__ float  g_h2[NB * 64 * 49];
__device__ float  g_feat[NB * 128];
__device__ float  g_part1[NB * 64];
__device__ float  g_part2[NB * 128];
__device__ float  g_bn1[64];
__device__ float  g_bn2[128];
__device__ float  g_fcpart[8 * NB * 128];
__device__ float  g_partA[64 * 129 * 129];
__device__ float  g_partB[64 * 1290];
__device__ double g_A[129 * 129];
__device__ double g_Bm[1290];
__device__ float  g_W[1290];

extern __shared__ char dynsmem[];

// ===== conv1 stats (recompute; nothing materialized) =====
__global__ __launch_bounds__(256) void k_conv1_stats(
    const float* __restrict__ x, const float* __restrict__ w, const float* __restrict__ bias)
{
    __shared__ float simg[900], sw[288], sb[32], wred[8][64];
    int n = blockIdx.x, tid = threadIdx.x;
    for (int i = tid; i < 900; i += 256) simg[i] = 0.f;
    for (int i = tid; i < 288; i += 256) sw[i] = w[i];
    if (tid < 32) sb[tid] = bias[tid];
    __syncthreads();
    const float* xi = x + n * 784;
    for (int i = tid; i < 784; i += 256)
        simg[(i / 28 + 1) * 30 + (i % 28) + 1] = xi[i];
    __syncthreads();

    float ls[32], lq[32];
#pragma unroll
    for (int c = 0; c < 32; c++) { ls[c] = 0.f; lq[c] = 0.f; }
    for (int p = tid; p < 784; p += 256) {
        int r = p / 28, c = p % 28;
        float patch[9];
#pragma unroll
        for (int ky = 0; ky < 3; ky++)
#pragma unroll
            for (int kx = 0; kx < 3; kx++) patch[ky * 3 + kx] = simg[(r + ky) * 30 + c + kx];
#pragma unroll
        for (int oc = 0; oc < 32; oc++) {
            float v = sb[oc];
#pragma unroll
            for (int t = 0; t < 9; t++) v = fmaf(sw[oc * 9 + t], patch[t], v);
            ls[oc] += v; lq[oc] = fmaf(v, v, lq[oc]);
        }
    }
    int lane = tid & 31, wid = tid >> 5;
#pragma unroll
    for (int oc = 0; oc < 32; oc++) {
        float s = ls[oc], q = lq[oc];
#pragma unroll
        for (int o = 16; o > 0; o >>= 1) {
            s += __shfl_down_sync(0xffffffffu, s, o);
            q += __shfl_down_sync(0xffffffffu, q, o);
        }
        if (lane == 0) { wred[wid][oc] = s; wred[wid][32 + oc] = q; }
    }
    __syncthreads();
    if (tid < 64) {
        float s = 0.f;
#pragma unroll
        for (int w8 = 0; w8 < 8; w8++) s += wred[w8][tid];
        g_part1[n * 64 + tid] = s;
    }
}

// ===== BN finalize (deterministic tree over per-image partials) =====
__global__ __launch_bounds__(256) void k_bnfinal(
    const float* __restrict__ gamma, const float* __restrict__ beta,
    const float* __restrict__ part, float* __restrict__ bn, int nc, float invN)
{
    int c = blockIdx.x, tid = threadIdx.x;
    float s = 0.f, q = 0.f;
    for (int r = tid; r < NB; r += 256) {
        s += part[r * 2 * nc + c];
        q += part[r * 2 * nc + nc + c];
    }
    __shared__ float ss[256], sq[256];
    ss[tid] = s; sq[tid] = q; __syncthreads();
    for (int o = 128; o > 0; o >>= 1) {
        if (tid < o) { ss[tid] += ss[tid + o]; sq[tid] += sq[tid + o]; }
        __syncthreads();
    }
    if (tid == 0) {
        float mean = ss[0] * invN;
        float var = sq[0] * invN - mean * mean;
        float scale = gamma[c] * rsqrtf(var + 1e-5f);
        bn[c] = scale;
        bn[nc + c] = beta[c] - mean * scale;
    }
}

// ===== conv1 + BN1 + relu + pool =====
__global__ __launch_bounds__(256) void k_conv1_pool(
    const float* __restrict__ x, const float* __restrict__ w, const float* __restrict__ bias)
{
    __shared__ float simg[900], sw[288], sb[32], ssc[32], ssh[32];
    int n = blockIdx.x, tid = threadIdx.x;
    for (int i = tid; i < 900; i += 256) simg[i] = 0.f;
    for (int i = tid; i < 288; i += 256) sw[i] = w[i];
    if (tid < 32) { sb[tid] = bias[tid]; ssc[tid] = g_bn1[tid]; ssh[tid] = g_bn1[32 + tid]; }
    __syncthreads();
    const float* xi = x + n * 784;
    for (int i = tid; i < 784; i += 256)
        simg[(i / 28 + 1) * 30 + (i % 28) + 1] = xi[i];
    __syncthreads();
    for (int o = tid; o < 32 * 196; o += 256) {
        int oc = o / 196, p = o % 196, py = p / 14, px = p % 14;
        float sc = ssc[oc], sh = ssh[oc], bb = sb[oc], m = 0.f;
#pragma unroll
        for (int dy = 0; dy < 2; dy++)
#pragma unroll
            for (int dx = 0; dx < 2; dx++) {
                int r = 2 * py + dy, c = 2 * px + dx;
                float v = bb;
#pragma unroll
                for (int ky = 0; ky < 3; ky++)
#pragma unroll
                    for (int kx = 0; kx < 3; kx++)
                        v = fmaf(sw[oc * 9 + ky * 3 + kx], simg[(r + ky) * 30 + c + kx], v);
                m = fmaxf(m, fmaxf(fmaf(sc, v, sh), 0.f));
            }
        g_h1[(n * 32 + oc) * 196 + p] = m;
    }
}

// ===== conv2 (FLOP wall) + per-image BN2 partials =====
__global__ __launch_bounds__(256, 2) void k_conv2(
    const float* __restrict__ cw, const float* __restrict__ cb)
{
    float* sw2 = (float*)dynsmem;            // 18432
    float* sin = sw2 + 18432;                // 8192 (32 ch x 16x16, zero-padded)
    int n = blockIdx.x, tid = threadIdx.x;
    for (int i = tid; i < 18432; i += 256) sw2[i] = cw[i];
    for (int i = tid; i < 8192; i += 256) sin[i] = 0.f;
    __syncthreads();
    const float* hp = g_h1 + n * 6272;
    for (int i = tid; i < 6272; i += 256) {
        int ci = i / 196, p = i % 196;
        sin[ci * 256 + (p / 14 + 1) * 16 + (p % 14 + 1)] = hp[i];
    }
    __syncthreads();

    float* op = g_out2 + n * 12544;
    float st[2][4];
    int nslots = 0;
    for (int s = tid; s < 448; s += 256) {       // slot = (oc pair, out row)
        int ocp = s / 14, oy = s % 14;
        float a0[14], a1[14];
#pragma unroll
        for (int xx = 0; xx < 14; xx++) { a0[xx] = 0.f; a1[xx] = 0.f; }
        const float* wb0 = sw2 + (2 * ocp) * 288;
        const float* wb1 = wb0 + 288;
        for (int ci = 0; ci < 32; ci++) {
            const float* ip = sin + ci * 256 + oy * 16;
            const float* w0p = wb0 + ci * 9;
            const float* w1p = wb1 + ci * 9;
#pragma unroll
            for (int ky = 0; ky < 3; ky++) {
                float rr[16];
#pragma unroll
                for (int j = 0; j < 16; j++) rr[j] = ip[ky * 16 + j];
#pragma unroll
                for (int kx = 0; kx < 3; kx++) {
                    float w0 = w0p[ky * 3 + kx], w1 = w1p[ky * 3 + kx];
#pragma unroll
                    for (int xx = 0; xx < 14; xx++) {
                        a0[xx] = fmaf(rr[xx + kx], w0, a0[xx]);
                        a1[xx] = fmaf(rr[xx + kx], w1, a1[xx]);
                    }
                }
            }
        }
        int oc0 = 2 * ocp;
        float b0 = cb[oc0], b1 = cb[oc0 + 1];
        float s0 = 0.f, q0 = 0.f, s1 = 0.f, q1 = 0.f;
#pragma unroll
        for (int xx = 0; xx < 14; xx++) {
            float v0 = a0[xx] + b0, v1 = a1[xx] + b1;
            op[(oc0 * 14 + oy) * 14 + xx] = v0;
            op[((oc0 + 1) * 14 + oy) * 14 + xx] = v1;
            s0 += v0; q0 = fmaf(v0, v0, q0);
            s1 += v1; q1 = fmaf(v1, v1, q1);
        }
        st[nslots][0] = s0; st[nslots][1] = q0; st[nslots][2] = s1; st[nslots][3] = q1;
        nslots++;
    }
    __syncthreads();
    float* sred = sin;                           // reuse, 448*4 floats
    {
        int k = 0;
        for (int s = tid; s < 448; s += 256) {
            sred[s * 4 + 0] = st[k][0]; sred[s * 4 + 1] = st[k][1];
            sred[s * 4 + 2] = st[k][2]; sred[s * 4 + 3] = st[k][3];
            k++;
        }
    }
    __syncthreads();
    if (tid < 64) {                              // fixed-order over 14 rows
        int ocp = tid >> 1, h = tid & 1;
        float s = 0.f, q = 0.f;
        for (int oy = 0; oy < 14; oy++) {
            int si = ocp * 14 + oy;
            s += sred[si * 4 + h * 2 + 0];
            q += sred[si * 4 + h * 2 + 1];
        }
        g_part2[n * 128 + tid] = s;
        g_part2[n * 128 + 64 + tid] = q;
    }
}

// ===== BN2 + relu + pool =====
__global__ __launch_bounds__(256) void k_bn2pool()
{
    int idx = blockIdx.x * 256 + threadIdx.x;
    if (idx >= NB * 64 * 49) return;
    int px = idx % 7, t = idx / 7;
    int py = t % 7; t /= 7;
    int oc = t % 64, n = t / 64;
    const float* base = g_out2 + (n * 64 + oc) * 196 + 2 * py * 14 + 2 * px;
    float sc = g_bn2[oc], sh = g_bn2[64 + oc];
    float r0 = fmaxf(fmaf(sc, base[0], sh), 0.f);
    float r1 = fmaxf(fmaf(sc, base[1], sh), 0.f);
    float r2 = fmaxf(fmaf(sc, base[14], sh), 0.f);
    float r3 = fmaxf(fmaf(sc, base[15], sh), 0.f);
    g_h2[idx] = fmaxf(fmaxf(r0, r1), fmaxf(r2, r3));
}

// ===== fc1: split-K(8) GEMM, partial buffers =====
__global__ __launch_bounds__(256) void k_fc1(const float* __restrict__ fw)
{
    __shared__ float As[32][65], Bs[32][130];
    int m0 = blockIdx.x * 64, z = blockIdx.y;
    int kt0 = ((98 * z) / 8) * 32, kt1 = ((98 * (z + 1)) / 8) * 32;
    int tid = threadIdx.x, tx = tid & 31, ty = tid >> 5;
    float acc[8][4];
#pragma unroll
    for (int u = 0; u < 8; u++)
#pragma unroll
        for (int v = 0; v < 4; v++) acc[u][v] = 0.f;
    for (int k0 = kt0; k0 < kt1; k0 += 32) {
        for (int i = tid; i < 2048; i += 256) {
            int r = i >> 5, c = i & 31;
            As[c][r] = g_h2[(m0 + r) * 3136 + k0 + c];
        }
        for (int i = tid; i < 4096; i += 256) {
            int r = i >> 5, c = i & 31;
            Bs[c][r] = fw[r * 3136 + k0 + c];
        }
        __syncthreads();
#pragma unroll
        for (int k = 0; k < 32; k++) {
            float a[8], b[4];
#pragma unroll
            for (int u = 0; u < 8; u++) a[u] = As[k][ty * 8 + u];
#pragma unroll
            for (int v = 0; v < 4; v++) b[v] = Bs[k][tx * 4 + v];
#pragma unroll
            for (int u = 0; u < 8; u++)
#pragma unroll
                for (int v = 0; v < 4; v++) acc[u][v] = fmaf(a[u], b[v], acc[u][v]);
        }
        __syncthreads();
    }
    float* pp = g_fcpart + z * (NB * 128);
#pragma unroll
    for (int u = 0; u < 8; u++)
#pragma unroll
        for (int v = 0; v < 4; v++)
            pp[(m0 + ty * 8 + u) * 128 + tx * 4 + v] = acc[u][v];
}

__global__ __launch_bounds__(256) void k_fc1combine(const float* __restrict__ fb)
{
    int idx = blockIdx.x * 256 + threadIdx.x;
    if (idx >= NB * 128) return;
    float v = fb[idx & 127];
#pragma unroll
    for (int z = 0; z < 8; z++) v += g_fcpart[z * (NB * 128) + idx];
    g_feat[idx] = fmaxf(v, 0.f);
}

// ===== SYRK chunk partials: Phi_chunk^T Phi_chunk =====
__global__ __launch_bounds__(256) void k_syrk()
{
    __shared__ float As[64][33], Bs[64][33];
    int ti = blockIdx.x, tj = blockIdx.y, ch = blockIdx.z;
    int tid = threadIdx.x, tx = tid & 15, ty = tid >> 4, n0 = ch * 64;
    for (int i = tid; i < 2048; i += 256) {
        int r = i >> 5, c = i & 31;
        int gi = ti * 32 + c, gj = tj * 32 + c;
        As[r][c] = (gi < 128) ? g_feat[(n0 + r) * 128 + gi] : (gi == 128 ? 1.f : 0.f);
        Bs[r][c] = (gj < 128) ? g_feat[(n0 + r) * 128 + gj] : (gj == 128 ? 1.f : 0.f);
    }
    __syncthreads();
    float a00 = 0.f, a01 = 0.f, a10 = 0.f, a11 = 0.f;
#pragma unroll 8
    for (int k = 0; k < 64; k++) {
        float x0 = As[k][2 * ty], x1 = As[k][2 * ty + 1];
        float y0 = Bs[k][2 * tx], y1 = Bs[k][2 * tx + 1];
        a00 = fmaf(x0, y0, a00); a01 = fmaf(x0, y1, a01);
        a10 = fmaf(x1, y0, a10); a11 = fmaf(x1, y1, a11);
    }
    float* pa = g_partA + ch * 16641;
    int gi0 = ti * 32 + 2 * ty, gj0 = tj * 32 + 2 * tx;
    if (gi0 < 129 && gj0 < 129) pa[gi0 * 129 + gj0] = a00;
    if (gi0 < 129 && gj0 + 1 < 129) pa[gi0 * 129 + gj0 + 1] = a01;
    if (gi0 + 1 < 129 && gj0 < 129) pa[(gi0 + 1) * 129 + gj0] = a10;
    if (gi0 + 1 < 129 && gj0 + 1 < 129) pa[(gi0 + 1) * 129 + gj0 + 1] = a11;
}

__global__ __launch_bounds__(256) void k_reduceA()
{
    int o = blockIdx.x * 256 + threadIdx.x;
    if (o >= 16641) return;
    double s = ((o / 129) == (o % 129)) ? 1.0 : 0.0;     // + I (P0^{-1})
    for (int ch = 0; ch < 64; ch++) s += (double)g_partA[ch * 16641 + o];
    g_A[o] = s;
}

// ===== Phi^T Y chunk partials =====
__global__ __launch_bounds__(256) void k_phity(const float* __restrict__ y)
{
    __shared__ float sf[64 * 129], sy[640];
    int ch = blockIdx.x, n0 = ch * 64, tid = threadIdx.x;
    for (int i = tid; i < 8192; i += 256)
        sf[(i >> 7) * 129 + (i & 127)] = g_feat[(n0 + (i >> 7)) * 128 + (i & 127)];
    for (int i = tid; i < 64; i += 256) sf[i * 129 + 128] = 1.f;
    for (int i = tid; i < 640; i += 256) sy[i] = y[n0 * 10 + i];
    __syncthreads();
    for (int o = tid; o < 1290; o += 256) {
        int i = o / 10, c = o % 10;
        float s = 0.f;
        for (int r = 0; r < 64; r++) s = fmaf(sf[r * 129 + i], sy[r * 10 + c], s);
        g_partB[ch * 1290 + o] = s;
    }
}

__global__ __launch_bounds__(256) void k_Bfinal(const float* __restrict__ Wrls)
{
    int o = blockIdx.x * 256 + threadIdx.x;
    if (o >= 1290) return;
    double s = (double)Wrls[o];
    for (int ch = 0; ch < 64; ch++) s += (double)g_partB[ch * 1290 + o];
    g_Bm[o] = s;
}

// ===== fp64 Cholesky + 10-RHS solve (single block) =====
__global__ __launch_bounds__(256) void k_chol(const float* __restrict__ Wrls,
                                              const int* __restrict__ sep)
{
    double* A = (double*)dynsmem;        // 129 x 130 padded
    double* Bv = A + 129 * 130;          // 129 x 10
    int tid = threadIdx.x;
    if (sep[0] == 0) {
        for (int i = tid; i < 1290; i += 256) g_W[i] = Wrls[i];
        return;
    }
    for (int i = tid; i < 16641; i += 256) A[(i / 129) * 130 + (i % 129)] = g_A[i];
    for (int i = tid; i < 1290; i += 256) Bv[i] = g_Bm[i];
    __syncthreads();
    __shared__ double sinv;
    for (int k = 0; k < 129; k++) {
        if (tid == 0) {
            double d = sqrt(A[k * 130 + k]);
            A[k * 130 + k] = d;
            sinv = 1.0 / d;
        }
        __syncthreads();
        double iv = sinv;
        for (int i = k + 1 + tid; i < 129; i += 256) A[i * 130 + k] *= iv;
        __syncthreads();
        int m = 128 - k;
        for (int t = tid; t < m * m; t += 256) {
            int i = k + 1 + t / m, j = k + 1 + t % m;
            A[i * 130 + j] -= A[i * 130 + k] * A[j * 130 + k];
        }
        __syncthreads();
    }
    // forward: L z = B
    for (int k = 0; k < 129; k++) {
        if (tid < 10) Bv[k * 10 + tid] /= A[k * 130 + k];
        __syncthreads();
        for (int t = tid; t < (128 - k) * 10; t += 256) {
            int i = k + 1 + t / 10, c = t % 10;
            Bv[i * 10 + c] -= A[i * 130 + k] * Bv[k * 10 + c];
        }
        __syncthreads();
    }
    // backward: L^T w = z
    for (int k = 128; k >= 0; k--) {
        if (tid < 10) Bv[k * 10 + tid] /= A[k * 130 + k];
        __syncthreads();
        for (int t = tid; t < k * 10; t += 256) {
            int i = t / 10, c = t % 10;
            Bv[i * 10 + c] -= A[k * 130 + i] * Bv[k * 10 + c];
        }
        __syncthreads();
    }
    for (int i = tid; i < 1290; i += 256) g_W[i] = (float)Bv[i];
}

// ===== head: out = feat @ W[:-1] + W[128] =====
__global__ __launch_bounds__(256) void k_head(float* __restrict__ out)
{
    __shared__ float sW[1290];
    int tid = threadIdx.x;
    for (int i = tid; i < 1290; i += 256) sW[i] = g_W[i];
    __syncthreads();
    int idx = blockIdx.x * 256 + tid;
    if (idx >= NB * 10) return;
    int n = idx / 10, c = idx % 10;
    float acc = sW[1280 + c];
    const float* f = g_feat + n * 128;
#pragma unroll 8
    for (int i = 0; i < 128; i++) acc = fmaf(f[i], sW[i * 10 + c], acc);
    out[idx] = acc;
}

extern "C" void kernel_launch(void* const* d_in, const int* in_sizes, int n_in,
                              void* d_out, int out_size)
{
    const float* x       = (const float*)d_in[0];
    const float* y       = (const float*)d_in[1];
    const float* conv1_w = (const float*)d_in[2];
    const float* conv1_b = (const float*)d_in[3];
    const float* bn1_g   = (const float*)d_in[4];
    const float* bn1_b   = (const float*)d_in[5];
    const float* conv2_w = (const float*)d_in[6];
    const float* conv2_b = (const float*)d_in[7];
    const float* bn2_g   = (const float*)d_in[8];
    const float* bn2_b   = (const float*)d_in[9];
    const float* fc1_w   = (const float*)d_in[10];
    const float* fc1_b   = (const float*)d_in[11];
    const float* W_rls   = (const float*)d_in[12];
    const int*   sep     = (const int*)d_in[14];
    float* out = (float*)d_out;

    cudaFuncSetAttribute(k_conv2, cudaFuncAttributeMaxDynamicSharedMemorySize, 106496);
    cudaFuncSetAttribute(k_chol, cudaFuncAttributeMaxDynamicSharedMemorySize, 144480);

    float* p1; cudaGetSymbolAddress((void**)&p1, g_part1);
    float* p2; cudaGetSymbolAddress((void**)&p2, g_part2);
    float* b1; cudaGetSymbolAddress((void**)&b1, g_bn1);
    float* b2; cudaGetSymbolAddress((void**)&b2, g_bn2);

    k_conv1_stats<<<NB, 256>>>(x, conv1_w, conv1_b);
    k_bnfinal<<<32, 256>>>(bn1_g, bn1_b, p1, b1, 32, 1.f / (float)(NB * 784));
    k_conv1_pool<<<NB, 256>>>(x, conv1_w, conv1_b);
    k_conv2<<<NB, 256, 106496>>>(conv2_w, conv2_b);
    k_bnfinal<<<64, 256>>>(bn2_g, bn2_b, p2, b2, 64, 1.f / (float)(NB * 196));
    k_bn2pool<<<(NB * 64 * 49 + 255) / 256, 256>>>();
    k_fc1<<<dim3(64, 8), 256>>>(fc1_w);
    k_fc1combine<<<(NB * 128) / 256, 256>>>(fc1_b);
    k_syrk<<<dim3(5, 5, 64), 256>>>();
    k_reduceA<<<66, 256>>>();
    k_phity<<<64, 256>>>(y);
    k_Bfinal<<<6, 256>>>(W_rls);
    k_chol<<<1, 256, 144480>>>(W_rls, sep);
    k_head<<<(NB * 10 + 255) / 256, 256>>>(out);
}

// round 3
// speedup vs baseline: 1.2690x; 1.2690x over previous
#include <cuda_runtime.h>
#include <math.h>

#define NB 4096

// ----- scratch (device globals; no allocations) -----
__device__ float  g_h1[NB * 32 * 196];
__device__ float  g_out2[NB * 64 * 196];
__device__ float  g_h2[NB * 64 * 49];
__device__ float  g_feat[NB * 128];
__device__ float  g_part1[NB * 64];
__device__ float  g_part2[NB * 128];
__device__ float  g_bn1[64];
__device__ float  g_bn2[128];
__device__ float  g_fcpart[8 * NB * 128];
__device__ float  g_partA[64 * 129 * 129];
__device__ float  g_partB[64 * 1290];
__device__ double g_A[129 * 129];
__device__ double g_Bm[1290];
__device__ float  g_W[1290];

extern __shared__ char dynsmem[];

// ===== conv1 stats (recompute; nothing materialized) =====
__global__ __launch_bounds__(256) void k_conv1_stats(
    const float* __restrict__ x, const float* __restrict__ w, const float* __restrict__ bias)
{
    __shared__ float simg[900], sw[288], sb[32], wred[8][64];
    int n = blockIdx.x, tid = threadIdx.x;
    for (int i = tid; i < 900; i += 256) simg[i] = 0.f;
    for (int i = tid; i < 288; i += 256) sw[i] = w[i];
    if (tid < 32) sb[tid] = bias[tid];
    __syncthreads();
    const float* xi = x + n * 784;
    for (int i = tid; i < 784; i += 256)
        simg[(i / 28 + 1) * 30 + (i % 28) + 1] = xi[i];
    __syncthreads();

    float ls[32], lq[32];
#pragma unroll
    for (int c = 0; c < 32; c++) { ls[c] = 0.f; lq[c] = 0.f; }
    for (int p = tid; p < 784; p += 256) {
        int r = p / 28, c = p % 28;
        float patch[9];
#pragma unroll
        for (int ky = 0; ky < 3; ky++)
#pragma unroll
            for (int kx = 0; kx < 3; kx++) patch[ky * 3 + kx] = simg[(r + ky) * 30 + c + kx];
#pragma unroll
        for (int oc = 0; oc < 32; oc++) {
            float v = sb[oc];
#pragma unroll
            for (int t = 0; t < 9; t++) v = fmaf(sw[oc * 9 + t], patch[t], v);
            ls[oc] += v; lq[oc] = fmaf(v, v, lq[oc]);
        }
    }
    int lane = tid & 31, wid = tid >> 5;
#pragma unroll
    for (int oc = 0; oc < 32; oc++) {
        float s = ls[oc], q = lq[oc];
#pragma unroll
        for (int o = 16; o > 0; o >>= 1) {
            s += __shfl_down_sync(0xffffffffu, s, o);
            q += __shfl_down_sync(0xffffffffu, q, o);
        }
        if (lane == 0) { wred[wid][oc] = s; wred[wid][32 + oc] = q; }
    }
    __syncthreads();
    if (tid < 64) {
        float s = 0.f;
#pragma unroll
        for (int w8 = 0; w8 < 8; w8++) s += wred[w8][tid];
        g_part1[n * 64 + tid] = s;
    }
}

// ===== BN finalize (deterministic tree over per-image partials) =====
__global__ __launch_bounds__(256) void k_bnfinal(
    const float* __restrict__ gamma, const float* __restrict__ beta,
    const float* __restrict__ part, float* __restrict__ bn, int nc, float invN)
{
    int c = blockIdx.x, tid = threadIdx.x;
    float s = 0.f, q = 0.f;
    for (int r = tid; r < NB; r += 256) {
        s += part[r * 2 * nc + c];
        q += part[r * 2 * nc + nc + c];
    }
    __shared__ float ss[256], sq[256];
    ss[tid] = s; sq[tid] = q; __syncthreads();
    for (int o = 128; o > 0; o >>= 1) {
        if (tid < o) { ss[tid] += ss[tid + o]; sq[tid] += sq[tid + o]; }
        __syncthreads();
    }
    if (tid == 0) {
        float mean = ss[0] * invN;
        float var = sq[0] * invN - mean * mean;
        float scale = gamma[c] * rsqrtf(var + 1e-5f);
        bn[c] = scale;
        bn[nc + c] = beta[c] - mean * scale;
    }
}

// ===== conv1 + BN1 + relu + pool =====
__global__ __launch_bounds__(256) void k_conv1_pool(
    const float* __restrict__ x, const float* __restrict__ w, const float* __restrict__ bias)
{
    __shared__ float simg[900], sw[288], sb[32], ssc[32], ssh[32];
    int n = blockIdx.x, tid = threadIdx.x;
    for (int i = tid; i < 900; i += 256) simg[i] = 0.f;
    for (int i = tid; i < 288; i += 256) sw[i] = w[i];
    if (tid < 32) { sb[tid] = bias[tid]; ssc[tid] = g_bn1[tid]; ssh[tid] = g_bn1[32 + tid]; }
    __syncthreads();
    const float* xi = x + n * 784;
    for (int i = tid; i < 784; i += 256)
        simg[(i / 28 + 1) * 30 + (i % 28) + 1] = xi[i];
    __syncthreads();
    for (int o = tid; o < 32 * 196; o += 256) {
        int oc = o / 196, p = o % 196, py = p / 14, px = p % 14;
        float sc = ssc[oc], sh = ssh[oc], bb = sb[oc], m = 0.f;
#pragma unroll
        for (int dy = 0; dy < 2; dy++)
#pragma unroll
            for (int dx = 0; dx < 2; dx++) {
                int r = 2 * py + dy, c = 2 * px + dx;
                float v = bb;
#pragma unroll
                for (int ky = 0; ky < 3; ky++)
#pragma unroll
                    for (int kx = 0; kx < 3; kx++)
                        v = fmaf(sw[oc * 9 + ky * 3 + kx], simg[(r + ky) * 30 + c + kx], v);
                m = fmaxf(m, fmaxf(fmaf(sc, v, sh), 0.f));
            }
        g_h1[(n * 32 + oc) * 196 + p] = m;
    }
}

// ===== conv2 (FLOP wall) + per-image BN2 partials =====
// 448 threads: slot = oy*32 + ocp. A warp = one output row across all 32 oc-pairs
//   -> input loads are warp-uniform broadcasts (bank-conflict free)
//   -> weight rows padded to stride 577 (577 mod 32 == 1) -> conflict-free
__global__ __launch_bounds__(448, 2) void k_conv2(
    const float* __restrict__ cw, const float* __restrict__ cb)
{
    float* sw2 = (float*)dynsmem;            // 32 ocp * 577
    float* sin = sw2 + 18464;                // 32 ch * 16*16 (zero-padded)
    int n = blockIdx.x, tid = threadIdx.x;
    for (int i = tid; i < 18432; i += 448) {
        int oc = i / 288, r = i % 288;
        sw2[(oc >> 1) * 577 + (oc & 1) * 288 + r] = cw[i];
    }
    for (int i = tid; i < 8192; i += 448) sin[i] = 0.f;
    __syncthreads();
    const float* hp = g_h1 + n * 6272;
    for (int i = tid; i < 6272; i += 448) {
        int ci = i / 196, p = i % 196;
        sin[ci * 256 + (p / 14 + 1) * 16 + (p % 14 + 1)] = hp[i];
    }
    __syncthreads();

    float* op = g_out2 + n * 12544;
    int oy = tid >> 5, ocp = tid & 31;       // slot = oy*32 + ocp

    float a0[14], a1[14];
#pragma unroll
    for (int xx = 0; xx < 14; xx++) { a0[xx] = 0.f; a1[xx] = 0.f; }
    const float* wb0 = sw2 + ocp * 577;
    const float* wb1 = wb0 + 288;
    for (int ci = 0; ci < 32; ci++) {
        const float* ip = sin + ci * 256 + oy * 16;
        const float* w0p = wb0 + ci * 9;
        const float* w1p = wb1 + ci * 9;
#pragma unroll
        for (int ky = 0; ky < 3; ky++) {
            float rr[16];
#pragma unroll
            for (int j = 0; j < 16; j++) rr[j] = ip[ky * 16 + j];
#pragma unroll
            for (int kx = 0; kx < 3; kx++) {
                float w0 = w0p[ky * 3 + kx], w1 = w1p[ky * 3 + kx];
#pragma unroll
                for (int xx = 0; xx < 14; xx++) {
                    a0[xx] = fmaf(rr[xx + kx], w0, a0[xx]);
                    a1[xx] = fmaf(rr[xx + kx], w1, a1[xx]);
                }
            }
        }
    }
    int oc0 = 2 * ocp;
    float b0 = cb[oc0], b1 = cb[oc0 + 1];
    float s0 = 0.f, q0 = 0.f, s1 = 0.f, q1 = 0.f;
#pragma unroll
    for (int xx = 0; xx < 14; xx++) {
        float v0 = a0[xx] + b0, v1 = a1[xx] + b1;
        op[(oc0 * 14 + oy) * 14 + xx] = v0;
        op[((oc0 + 1) * 14 + oy) * 14 + xx] = v1;
        s0 += v0; q0 = fmaf(v0, v0, q0);
        s1 += v1; q1 = fmaf(v1, v1, q1);
    }
    __syncthreads();                          // sin reads done -> reuse
    float* sred = sin;                        // 448*4 floats
    sred[tid * 4 + 0] = s0; sred[tid * 4 + 1] = q0;
    sred[tid * 4 + 2] = s1; sred[tid * 4 + 3] = q1;
    __syncthreads();
    if (tid < 64) {                           // oc = tid, fixed order over 14 rows
        int p = tid >> 1, h = tid & 1;
        float s = 0.f, q = 0.f;
        for (int r = 0; r < 14; r++) {
            int si = r * 32 + p;
            s += sred[si * 4 + h * 2 + 0];
            q += sred[si * 4 + h * 2 + 1];
        }
        g_part2[n * 128 + tid] = s;
        g_part2[n * 128 + 64 + tid] = q;
    }
}

// ===== BN2 + relu + pool =====
__global__ __launch_bounds__(256) void k_bn2pool()
{
    int idx = blockIdx.x * 256 + threadIdx.x;
    if (idx >= NB * 64 * 49) return;
    int px = idx % 7, t = idx / 7;
    int py = t % 7; t /= 7;
    int oc = t % 64, n = t / 64;
    const float* base = g_out2 + (n * 64 + oc) * 196 + 2 * py * 14 + 2 * px;
    float sc = g_bn2[oc], sh = g_bn2[64 + oc];
    float r0 = fmaxf(fmaf(sc, base[0], sh), 0.f);
    float r1 = fmaxf(fmaf(sc, base[1], sh), 0.f);
    float r2 = fmaxf(fmaf(sc, base[14], sh), 0.f);
    float r3 = fmaxf(fmaf(sc, base[15], sh), 0.f);
    g_h2[idx] = fmaxf(fmaxf(r0, r1), fmaxf(r2, r3));
}

// ===== fc1: split-K(8) GEMM, partial buffers =====
__global__ __launch_bounds__(256) void k_fc1(const float* __restrict__ fw)
{
    __shared__ float As[32][65], Bs[32][130];
    int m0 = blockIdx.x * 64, z = blockIdx.y;
    int kt0 = ((98 * z) / 8) * 32, kt1 = ((98 * (z + 1)) / 8) * 32;
    int tid = threadIdx.x, tx = tid & 31, ty = tid >> 5;
    float acc[8][4];
#pragma unroll
    for (int u = 0; u < 8; u++)
#pragma unroll
        for (int v = 0; v < 4; v++) acc[u][v] = 0.f;
    for (int k0 = kt0; k0 < kt1; k0 += 32) {
        for (int i = tid; i < 2048; i += 256) {
            int r = i >> 5, c = i & 31;
            As[c][r] = g_h2[(m0 + r) * 3136 + k0 + c];
        }
        for (int i = tid; i < 4096; i += 256) {
            int r = i >> 5, c = i & 31;
            Bs[c][r] = fw[r * 3136 + k0 + c];
        }
        __syncthreads();
#pragma unroll
        for (int k = 0; k < 32; k++) {
            float a[8], b[4];
#pragma unroll
            for (int u = 0; u < 8; u++) a[u] = As[k][ty * 8 + u];
#pragma unroll
            for (int v = 0; v < 4; v++) b[v] = Bs[k][tx * 4 + v];
#pragma unroll
            for (int u = 0; u < 8; u++)
#pragma unroll
                for (int v = 0; v < 4; v++) acc[u][v] = fmaf(a[u], b[v], acc[u][v]);
        }
        __syncthreads();
    }
    float* pp = g_fcpart + z * (NB * 128);
#pragma unroll
    for (int u = 0; u < 8; u++)
#pragma unroll
        for (int v = 0; v < 4; v++)
            pp[(m0 + ty * 8 + u) * 128 + tx * 4 + v] = acc[u][v];
}

__global__ __launch_bounds__(256) void k_fc1combine(const float* __restrict__ fb)
{
    int idx = blockIdx.x * 256 + threadIdx.x;
    if (idx >= NB * 128) return;
    float v = fb[idx & 127];
#pragma unroll
    for (int z = 0; z < 8; z++) v += g_fcpart[z * (NB * 128) + idx];
    g_feat[idx] = fmaxf(v, 0.f);
}

// ===== SYRK chunk partials: Phi_chunk^T Phi_chunk =====
__global__ __launch_bounds__(256) void k_syrk()
{
    __shared__ float As[64][33], Bs[64][33];
    int ti = blockIdx.x, tj = blockIdx.y, ch = blockIdx.z;
    int tid = threadIdx.x, tx = tid & 15, ty = tid >> 4, n0 = ch * 64;
    for (int i = tid; i < 2048; i += 256) {
        int r = i >> 5, c = i & 31;
        int gi = ti * 32 + c, gj = tj * 32 + c;
        As[r][c] = (gi < 128) ? g_feat[(n0 + r) * 128 + gi] : (gi == 128 ? 1.f : 0.f);
        Bs[r][c] = (gj < 128) ? g_feat[(n0 + r) * 128 + gj] : (gj == 128 ? 1.f : 0.f);
    }
    __syncthreads();
    float a00 = 0.f, a01 = 0.f, a10 = 0.f, a11 = 0.f;
#pragma unroll 8
    for (int k = 0; k < 64; k++) {
        float x0 = As[k][2 * ty], x1 = As[k][2 * ty + 1];
        float y0 = Bs[k][2 * tx], y1 = Bs[k][2 * tx + 1];
        a00 = fmaf(x0, y0, a00); a01 = fmaf(x0, y1, a01);
        a10 = fmaf(x1, y0, a10); a11 = fmaf(x1, y1, a11);
    }
    float* pa = g_partA + ch * 16641;
    int gi0 = ti * 32 + 2 * ty, gj0 = tj * 32 + 2 * tx;
    if (gi0 < 129 && gj0 < 129) pa[gi0 * 129 + gj0] = a00;
    if (gi0 < 129 && gj0 + 1 < 129) pa[gi0 * 129 + gj0 + 1] = a01;
    if (gi0 + 1 < 129 && gj0 < 129) pa[(gi0 + 1) * 129 + gj0] = a10;
    if (gi0 + 1 < 129 && gj0 + 1 < 129) pa[(gi0 + 1) * 129 + gj0 + 1] = a11;
}

__global__ __launch_bounds__(256) void k_reduceA()
{
    int o = blockIdx.x * 256 + threadIdx.x;
    if (o >= 16641) return;
    double s = ((o / 129) == (o % 129)) ? 1.0 : 0.0;     // + I (P0^{-1})
    for (int ch = 0; ch < 64; ch++) s += (double)g_partA[ch * 16641 + o];
    g_A[o] = s;
}

// ===== Phi^T Y chunk partials =====
__global__ __launch_bounds__(256) void k_phity(const float* __restrict__ y)
{
    __shared__ float sf[64 * 129], sy[640];
    int ch = blockIdx.x, n0 = ch * 64, tid = threadIdx.x;
    for (int i = tid; i < 8192; i += 256)
        sf[(i >> 7) * 129 + (i & 127)] = g_feat[(n0 + (i >> 7)) * 128 + (i & 127)];
    for (int i = tid; i < 64; i += 256) sf[i * 129 + 128] = 1.f;
    for (int i = tid; i < 640; i += 256) sy[i] = y[n0 * 10 + i];
    __syncthreads();
    for (int o = tid; o < 1290; o += 256) {
        int i = o / 10, c = o % 10;
        float s = 0.f;
        for (int r = 0; r < 64; r++) s = fmaf(sf[r * 129 + i], sy[r * 10 + c], s);
        g_partB[ch * 1290 + o] = s;
    }
}

__global__ __launch_bounds__(256) void k_Bfinal(const float* __restrict__ Wrls)
{
    int o = blockIdx.x * 256 + threadIdx.x;
    if (o >= 1290) return;
    double s = (double)Wrls[o];
    for (int ch = 0; ch < 64; ch++) s += (double)g_partB[ch * 1290 + o];
    g_Bm[o] = s;
}

// ===== fp64 Cholesky + 10-RHS solve (single block) =====
__global__ __launch_bounds__(256) void k_chol(const float* __restrict__ Wrls,
                                              const int* __restrict__ sep)
{
    double* A = (double*)dynsmem;        // 129 x 130 padded
    double* Bv = A + 129 * 130;          // 129 x 10
    int tid = threadIdx.x;
    if (sep[0] == 0) {
        for (int i = tid; i < 1290; i += 256) g_W[i] = Wrls[i];
        return;
    }
    for (int i = tid; i < 16641; i += 256) A[(i / 129) * 130 + (i % 129)] = g_A[i];
    for (int i = tid; i < 1290; i += 256) Bv[i] = g_Bm[i];
    __syncthreads();
    __shared__ double sinv;
    for (int k = 0; k < 129; k++) {
        if (tid == 0) {
            double d = sqrt(A[k * 130 + k]);
            A[k * 130 + k] = d;
            sinv = 1.0 / d;
        }
        __syncthreads();
        double iv = sinv;
        for (int i = k + 1 + tid; i < 129; i += 256) A[i * 130 + k] *= iv;
        __syncthreads();
        int m = 128 - k;
        for (int t = tid; t < m * m; t += 256) {
            int i = k + 1 + t / m, j = k + 1 + t % m;
            A[i * 130 + j] -= A[i * 130 + k] * A[j * 130 + k];
        }
        __syncthreads();
    }
    for (int k = 0; k < 129; k++) {
        if (tid < 10) Bv[k * 10 + tid] /= A[k * 130 + k];
        __syncthreads();
        for (int t = tid; t < (128 - k) * 10; t += 256) {
            int i = k + 1 + t / 10, c = t % 10;
            Bv[i * 10 + c] -= A[i * 130 + k] * Bv[k * 10 + c];
        }
        __syncthreads();
    }
    for (int k = 128; k >= 0; k--) {
        if (tid < 10) Bv[k * 10 + tid] /= A[k * 130 + k];
        __syncthreads();
        for (int t = tid; t < k * 10; t += 256) {
            int i = t / 10, c = t % 10;
            Bv[i * 10 + c] -= A[k * 130 + i] * Bv[k * 10 + c];
        }
        __syncthreads();
    }
    for (int i = tid; i < 1290; i += 256) g_W[i] = (float)Bv[i];
}

// ===== head: out = feat @ W[:-1] + W[128] =====
__global__ __launch_bounds__(256) void k_head(float* __restrict__ out)
{
    __shared__ float sW[1290];
    int tid = threadIdx.x;
    for (int i = tid; i < 1290; i += 256) sW[i] = g_W[i];
    __syncthreads();
    int idx = blockIdx.x * 256 + tid;
    if (idx >= NB * 10) return;
    int n = idx / 10, c = idx % 10;
    float acc = sW[1280 + c];
    const float* f = g_feat + n * 128;
#pragma unroll 8
    for (int i = 0; i < 128; i++) acc = fmaf(f[i], sW[i * 10 + c], acc);
    out[idx] = acc;
}

extern "C" void kernel_launch(void* const* d_in, const int* in_sizes, int n_in,
                              void* d_out, int out_size)
{
    const float* x       = (const float*)d_in[0];
    const float* y       = (const float*)d_in[1];
    const float* conv1_w = (const float*)d_in[2];
    const float* conv1_b = (const float*)d_in[3];
    const float* bn1_g   = (const float*)d_in[4];
    const float* bn1_b   = (const float*)d_in[5];
    const float* conv2_w = (const float*)d_in[6];
    const float* conv2_b = (const float*)d_in[7];
    const float* bn2_g   = (const float*)d_in[8];
    const float* bn2_b   = (const float*)d_in[9];
    const float* fc1_w   = (const float*)d_in[10];
    const float* fc1_b   = (const float*)d_in[11];
    const float* W_rls   = (const float*)d_in[12];
    const int*   sep     = (const int*)d_in[14];
    float* out = (float*)d_out;

    cudaFuncSetAttribute(k_conv2, cudaFuncAttributeMaxDynamicSharedMemorySize, 106624);
    cudaFuncSetAttribute(k_chol, cudaFuncAttributeMaxDynamicSharedMemorySize, 144480);

    float* p1; cudaGetSymbolAddress((void**)&p1, g_part1);
    float* p2; cudaGetSymbolAddress((void**)&p2, g_part2);
    float* b1; cudaGetSymbolAddress((void**)&b1, g_bn1);
    float* b2; cudaGetSymbolAddress((void**)&b2, g_bn2);

    k_conv1_stats<<<NB, 256>>>(x, conv1_w, conv1_b);
    k_bnfinal<<<32, 256>>>(bn1_g, bn1_b, p1, b1, 32, 1.f / (float)(NB * 784));
    k_conv1_pool<<<NB, 256>>>(x, conv1_w, conv1_b);
    k_conv2<<<NB, 448, 106624>>>(conv2_w, conv2_b);
    k_bnfinal<<<64, 256>>>(bn2_g, bn2_b, p2, b2, 64, 1.f / (float)(NB * 196));
    k_bn2pool<<<(NB * 64 * 49 + 255) / 256, 256>>>();
    k_fc1<<<dim3(64, 8), 256>>>(fc1_w);
    k_fc1combine<<<(NB * 128) / 256, 256>>>(fc1_b);
    k_syrk<<<dim3(5, 5, 64), 256>>>();
    k_reduceA<<<66, 256>>>();
    k_phity<<<64, 256>>>(y);
    k_Bfinal<<<6, 256>>>(W_rls);
    k_chol<<<1, 256, 144480>>>(W_rls, sep);
    k_head<<<(NB * 10 + 255) / 256, 256>>>(out);
}

// round 4
// speedup vs baseline: 1.2781x; 1.0072x over previous
#include <cuda_runtime.h>
#include <math.h>

#define NB 4096

// ----- scratch (device globals; no allocations) -----
__device__ float  g_h1[NB * 32 * 196];
__device__ float  g_out2[NB * 64 * 196];
__device__ float  g_feat[NB * 128];
__device__ float  g_part1[NB * 64];
__device__ float  g_part2[NB * 128];
__device__ float  g_bn1[64];
__device__ float  g_bn2[128];
__device__ float  g_fcpart[8 * NB * 128];
__device__ float  g_partA[64 * 129 * 129];
__device__ float  g_partB[64 * 1290];
__device__ double g_A[129 * 129];
__device__ double g_Bm[1290];
__device__ float  g_W[1290];

extern __shared__ char dynsmem[];

union F2 { unsigned long long u; float2 f; };

__device__ __forceinline__ void fma2(unsigned long long& acc,
                                     unsigned long long x, unsigned long long w)
{
    asm("fma.rn.f32x2 %0, %1, %2, %0;" : "+l"(acc) : "l"(x), "l"(w));
}

// ===== conv1 stats (recompute; nothing materialized) =====
__global__ __launch_bounds__(256) void k_conv1_stats(
    const float* __restrict__ x, const float* __restrict__ w, const float* __restrict__ bias)
{
    __shared__ float simg[900], sw[288], sb[32], wred[8][64];
    int n = blockIdx.x, tid = threadIdx.x;
    for (int i = tid; i < 900; i += 256) simg[i] = 0.f;
    for (int i = tid; i < 288; i += 256) sw[i] = w[i];
    if (tid < 32) sb[tid] = bias[tid];
    __syncthreads();
    const float* xi = x + n * 784;
    for (int i = tid; i < 784; i += 256)
        simg[(i / 28 + 1) * 30 + (i % 28) + 1] = xi[i];
    __syncthreads();

    float ls[32], lq[32];
#pragma unroll
    for (int c = 0; c < 32; c++) { ls[c] = 0.f; lq[c] = 0.f; }
    for (int p = tid; p < 784; p += 256) {
        int r = p / 28, c = p % 28;
        float patch[9];
#pragma unroll
        for (int ky = 0; ky < 3; ky++)
#pragma unroll
            for (int kx = 0; kx < 3; kx++) patch[ky * 3 + kx] = simg[(r + ky) * 30 + c + kx];
#pragma unroll
        for (int oc = 0; oc < 32; oc++) {
            float v = sb[oc];
#pragma unroll
            for (int t = 0; t < 9; t++) v = fmaf(sw[oc * 9 + t], patch[t], v);
            ls[oc] += v; lq[oc] = fmaf(v, v, lq[oc]);
        }
    }
    int lane = tid & 31, wid = tid >> 5;
#pragma unroll
    for (int oc = 0; oc < 32; oc++) {
        float s = ls[oc], q = lq[oc];
#pragma unroll
        for (int o = 16; o > 0; o >>= 1) {
            s += __shfl_down_sync(0xffffffffu, s, o);
            q += __shfl_down_sync(0xffffffffu, q, o);
        }
        if (lane == 0) { wred[wid][oc] = s; wred[wid][32 + oc] = q; }
    }
    __syncthreads();
    if (tid < 64) {
        float s = 0.f;
#pragma unroll
        for (int w8 = 0; w8 < 8; w8++) s += wred[w8][tid];
        g_part1[n * 64 + tid] = s;
    }
}

// ===== BN finalize =====
__global__ __launch_bounds__(256) void k_bnfinal(
    const float* __restrict__ gamma, const float* __restrict__ beta,
    const float* __restrict__ part, float* __restrict__ bn, int nc, float invN)
{
    int c = blockIdx.x, tid = threadIdx.x;
    float s = 0.f, q = 0.f;
    for (int r = tid; r < NB; r += 256) {
        s += part[r * 2 * nc + c];
        q += part[r * 2 * nc + nc + c];
    }
    __shared__ float ss[256], sq[256];
    ss[tid] = s; sq[tid] = q; __syncthreads();
    for (int o = 128; o > 0; o >>= 1) {
        if (tid < o) { ss[tid] += ss[tid + o]; sq[tid] += sq[tid + o]; }
        __syncthreads();
    }
    if (tid == 0) {
        float mean = ss[0] * invN;
        float var = sq[0] * invN - mean * mean;
        float scale = gamma[c] * rsqrtf(var + 1e-5f);
        bn[c] = scale;
        bn[nc + c] = beta[c] - mean * scale;
    }
}

// ===== conv1 + BN1 + relu + pool =====
__global__ __launch_bounds__(256) void k_conv1_pool(
    const float* __restrict__ x, const float* __restrict__ w, const float* __restrict__ bias)
{
    __shared__ float simg[900], sw[288], sb[32], ssc[32], ssh[32];
    int n = blockIdx.x, tid = threadIdx.x;
    for (int i = tid; i < 900; i += 256) simg[i] = 0.f;
    for (int i = tid; i < 288; i += 256) sw[i] = w[i];
    if (tid < 32) { sb[tid] = bias[tid]; ssc[tid] = g_bn1[tid]; ssh[tid] = g_bn1[32 + tid]; }
    __syncthreads();
    const float* xi = x + n * 784;
    for (int i = tid; i < 784; i += 256)
        simg[(i / 28 + 1) * 30 + (i % 28) + 1] = xi[i];
    __syncthreads();
    for (int o = tid; o < 32 * 196; o += 256) {
        int oc = o / 196, p = o % 196, py = p / 14, px = p % 14;
        float sc = ssc[oc], sh = ssh[oc], bb = sb[oc], m = 0.f;
#pragma unroll
        for (int dy = 0; dy < 2; dy++)
#pragma unroll
            for (int dx = 0; dx < 2; dx++) {
                int r = 2 * py + dy, c = 2 * px + dx;
                float v = bb;
#pragma unroll
                for (int ky = 0; ky < 3; ky++)
#pragma unroll
                    for (int kx = 0; kx < 3; kx++)
                        v = fmaf(sw[oc * 9 + ky * 3 + kx], simg[(r + ky) * 30 + c + kx], v);
                m = fmaxf(m, fmaxf(fmaf(sc, v, sh), 0.f));
            }
        g_h1[(n * 32 + oc) * 196 + p] = m;
    }
}

// ===== conv2 with packed f32x2 FMA (dual-issue fp32) =====
// 448 thr: slot = oy*32 + ocp. Warp-uniform input rows (broadcast LDS.128),
// weights padded stride 577 (conflict-free). 14 outputs as 7 f32x2 pairs:
//   kx=0 -> E[j], kx=1 -> odd pairs O[j] (packed), kx=2 -> E[j+1].
__global__ __launch_bounds__(448, 2) void k_conv2(
    const float* __restrict__ cw, const float* __restrict__ cb)
{
    float* sw2 = (float*)dynsmem;            // 32 * 577
    float* sin = sw2 + 18464;                // 32 ch * 256 (16x16 zero-padded)
    int n = blockIdx.x, tid = threadIdx.x;
    for (int i = tid; i < 18432; i += 448) {
        int oc = i / 288, r = i % 288;
        sw2[(oc >> 1) * 577 + (oc & 1) * 288 + r] = cw[i];
    }
    for (int i = tid; i < 8192; i += 448) sin[i] = 0.f;
    __syncthreads();
    const float* hp = g_h1 + n * 6272;
    for (int i = tid; i < 6272; i += 448) {
        int ci = i / 196, p = i % 196;
        sin[ci * 256 + (p / 14 + 1) * 16 + (p % 14 + 1)] = hp[i];
    }
    __syncthreads();

    float* op = g_out2 + n * 12544;
    int oy = tid >> 5, ocp = tid & 31;

    unsigned long long a0[7], a1[7];
#pragma unroll
    for (int j = 0; j < 7; j++) { a0[j] = 0ull; a1[j] = 0ull; }
    const float* wb0 = sw2 + ocp * 577;
    const float* wb1 = wb0 + 288;

    for (int ci = 0; ci < 32; ci++) {
        const float* ip = sin + ci * 256 + oy * 16;
        const float* w0p = wb0 + ci * 9;
        const float* w1p = wb1 + ci * 9;
#pragma unroll
        for (int ky = 0; ky < 3; ky++) {
            const ulonglong2* rp = (const ulonglong2*)(ip + ky * 16);
            ulonglong2 u01 = rp[0], u23 = rp[1], u45 = rp[2], u67 = rp[3];
            F2 E[8];
            E[0].u = u01.x; E[1].u = u01.y; E[2].u = u23.x; E[3].u = u23.y;
            E[4].u = u45.x; E[5].u = u45.y; E[6].u = u67.x; E[7].u = u67.y;
            F2 O[7];
#pragma unroll
            for (int j = 0; j < 7; j++) {
                O[j].f.x = E[j].f.y;
                O[j].f.y = E[j + 1].f.x;
            }
            F2 W00, W01, W02, W10, W11, W12;
            float w0a = w0p[ky * 3 + 0], w0b = w0p[ky * 3 + 1], w0c = w0p[ky * 3 + 2];
            float w1a = w1p[ky * 3 + 0], w1b = w1p[ky * 3 + 1], w1c = w1p[ky * 3 + 2];
            W00.f = make_float2(w0a, w0a); W01.f = make_float2(w0b, w0b);
            W02.f = make_float2(w0c, w0c); W10.f = make_float2(w1a, w1a);
            W11.f = make_float2(w1b, w1b); W12.f = make_float2(w1c, w1c);
#pragma unroll
            for (int j = 0; j < 7; j++) {
                fma2(a0[j], E[j].u,     W00.u);
                fma2(a0[j], O[j].u,     W01.u);
                fma2(a0[j], E[j + 1].u, W02.u);
                fma2(a1[j], E[j].u,     W10.u);
                fma2(a1[j], O[j].u,     W11.u);
                fma2(a1[j], E[j + 1].u, W12.u);
            }
        }
    }

    int oc0 = 2 * ocp;
    float b0 = cb[oc0], b1 = cb[oc0 + 1];
    float s0 = 0.f, q0 = 0.f, s1 = 0.f, q1 = 0.f;
    float* r0 = op + (oc0 * 14 + oy) * 14;
    float* r1 = op + ((oc0 + 1) * 14 + oy) * 14;
#pragma unroll
    for (int j = 0; j < 7; j++) {
        F2 t0, t1; t0.u = a0[j]; t1.u = a1[j];
        float v0a = t0.f.x + b0, v0b = t0.f.y + b0;
        float v1a = t1.f.x + b1, v1b = t1.f.y + b1;
        r0[2 * j] = v0a; r0[2 * j + 1] = v0b;
        r1[2 * j] = v1a; r1[2 * j + 1] = v1b;
        s0 += v0a + v0b; q0 = fmaf(v0a, v0a, fmaf(v0b, v0b, q0));
        s1 += v1a + v1b; q1 = fmaf(v1a, v1a, fmaf(v1b, v1b, q1));
    }
    __syncthreads();                          // sin reads done -> reuse
    float* sred = sin;
    sred[tid * 4 + 0] = s0; sred[tid * 4 + 1] = q0;
    sred[tid * 4 + 2] = s1; sred[tid * 4 + 3] = q1;
    __syncthreads();
    if (tid < 64) {
        int p = tid >> 1, h = tid & 1;
        float s = 0.f, q = 0.f;
        for (int r = 0; r < 14; r++) {
            int si = r * 32 + p;
            s += sred[si * 4 + h * 2 + 0];
            q += sred[si * 4 + h * 2 + 1];
        }
        g_part2[n * 128 + tid] = s;
        g_part2[n * 128 + 64 + tid] = q;
    }
}

// ===== fc1 (BN2+relu+pool fused into the A-tile load) =====
__global__ __launch_bounds__(256) void k_fc1(const float* __restrict__ fw)
{
    __shared__ float As[32][65], Bs[32][130];
    int m0 = blockIdx.x * 64, z = blockIdx.y;
    int kt0 = ((98 * z) / 8) * 32, kt1 = ((98 * (z + 1)) / 8) * 32;
    int tid = threadIdx.x, tx = tid & 31, ty = tid >> 5;
    float acc[8][4];
#pragma unroll
    for (int u = 0; u < 8; u++)
#pragma unroll
        for (int v = 0; v < 4; v++) acc[u][v] = 0.f;
    for (int k0 = kt0; k0 < kt1; k0 += 32) {
        for (int i = tid; i < 2048; i += 256) {
            int r = i >> 5, c = i & 31;
            int kk = k0 + c;
            int oc = kk / 49, p = kk - oc * 49, py = p / 7, px = p - py * 7;
            const float* base = g_out2 + ((m0 + r) * 64 + oc) * 196 + 2 * py * 14 + 2 * px;
            float sc = __ldg(&g_bn2[oc]), sh = __ldg(&g_bn2[64 + oc]);
            float v = fmaxf(fmaf(sc, base[0], sh), 0.f);
            v = fmaxf(v, fmaxf(fmaf(sc, base[1], sh), 0.f));
            v = fmaxf(v, fmaxf(fmaf(sc, base[14], sh), 0.f));
            v = fmaxf(v, fmaxf(fmaf(sc, base[15], sh), 0.f));
            As[c][r] = v;
        }
        for (int i = tid; i < 4096; i += 256) {
            int r = i >> 5, c = i & 31;
            Bs[c][r] = fw[r * 3136 + k0 + c];
        }
        __syncthreads();
#pragma unroll
        for (int k = 0; k < 32; k++) {
            float a[8], b[4];
#pragma unroll
            for (int u = 0; u < 8; u++) a[u] = As[k][ty * 8 + u];
#pragma unroll
            for (int v = 0; v < 4; v++) b[v] = Bs[k][tx * 4 + v];
#pragma unroll
            for (int u = 0; u < 8; u++)
#pragma unroll
                for (int v = 0; v < 4; v++) acc[u][v] = fmaf(a[u], b[v], acc[u][v]);
        }
        __syncthreads();
    }
    float* pp = g_fcpart + z * (NB * 128);
#pragma unroll
    for (int u = 0; u < 8; u++)
#pragma unroll
        for (int v = 0; v < 4; v++)
            pp[(m0 + ty * 8 + u) * 128 + tx * 4 + v] = acc[u][v];
}

__global__ __launch_bounds__(256) void k_fc1combine(const float* __restrict__ fb)
{
    int idx = blockIdx.x * 256 + threadIdx.x;
    if (idx >= NB * 128) return;
    float v = fb[idx & 127];
#pragma unroll
    for (int z = 0; z < 8; z++) v += g_fcpart[z * (NB * 128) + idx];
    g_feat[idx] = fmaxf(v, 0.f);
}

// ===== SYRK chunk partials =====
__global__ __launch_bounds__(256) void k_syrk()
{
    __shared__ float As[64][33], Bs[64][33];
    int ti = blockIdx.x, tj = blockIdx.y, ch = blockIdx.z;
    int tid = threadIdx.x, tx = tid & 15, ty = tid >> 4, n0 = ch * 64;
    for (int i = tid; i < 2048; i += 256) {
        int r = i >> 5, c = i & 31;
        int gi = ti * 32 + c, gj = tj * 32 + c;
        As[r][c] = (gi < 128) ? g_feat[(n0 + r) * 128 + gi] : (gi == 128 ? 1.f : 0.f);
        Bs[r][c] = (gj < 128) ? g_feat[(n0 + r) * 128 + gj] : (gj == 128 ? 1.f : 0.f);
    }
    __syncthreads();
    float a00 = 0.f, a01 = 0.f, a10 = 0.f, a11 = 0.f;
#pragma unroll 8
    for (int k = 0; k < 64; k++) {
        float x0 = As[k][2 * ty], x1 = As[k][2 * ty + 1];
        float y0 = Bs[k][2 * tx], y1 = Bs[k][2 * tx + 1];
        a00 = fmaf(x0, y0, a00); a01 = fmaf(x0, y1, a01);
        a10 = fmaf(x1, y0, a10); a11 = fmaf(x1, y1, a11);
    }
    float* pa = g_partA + ch * 16641;
    int gi0 = ti * 32 + 2 * ty, gj0 = tj * 32 + 2 * tx;
    if (gi0 < 129 && gj0 < 129) pa[gi0 * 129 + gj0] = a00;
    if (gi0 < 129 && gj0 + 1 < 129) pa[gi0 * 129 + gj0 + 1] = a01;
    if (gi0 + 1 < 129 && gj0 < 129) pa[(gi0 + 1) * 129 + gj0] = a10;
    if (gi0 + 1 < 129 && gj0 + 1 < 129) pa[(gi0 + 1) * 129 + gj0 + 1] = a11;
}

__global__ __launch_bounds__(256) void k_reduceA()
{
    int o = blockIdx.x * 256 + threadIdx.x;
    if (o >= 16641) return;
    double s = ((o / 129) == (o % 129)) ? 1.0 : 0.0;
    for (int ch = 0; ch < 64; ch++) s += (double)g_partA[ch * 16641 + o];
    g_A[o] = s;
}

// ===== Phi^T Y chunk partials =====
__global__ __launch_bounds__(256) void k_phity(const float* __restrict__ y)
{
    __shared__ float sf[64 * 129], sy[640];
    int ch = blockIdx.x, n0 = ch * 64, tid = threadIdx.x;
    for (int i = tid; i < 8192; i += 256)
        sf[(i >> 7) * 129 + (i & 127)] = g_feat[(n0 + (i >> 7)) * 128 + (i & 127)];
    for (int i = tid; i < 64; i += 256) sf[i * 129 + 128] = 1.f;
    for (int i = tid; i < 640; i += 256) sy[i] = y[n0 * 10 + i];
    __syncthreads();
    for (int o = tid; o < 1290; o += 256) {
        int i = o / 10, c = o % 10;
        float s = 0.f;
        for (int r = 0; r < 64; r++) s = fmaf(sf[r * 129 + i], sy[r * 10 + c], s);
        g_partB[ch * 1290 + o] = s;
    }
}

__global__ __launch_bounds__(256) void k_Bfinal(const float* __restrict__ Wrls)
{
    int o = blockIdx.x * 256 + threadIdx.x;
    if (o >= 1290) return;
    double s = (double)Wrls[o];
    for (int ch = 0; ch < 64; ch++) s += (double)g_partB[ch * 1290 + o];
    g_Bm[o] = s;
}

// ===== fp64 Cholesky + 10-RHS solve =====
__global__ __launch_bounds__(256) void k_chol(const float* __restrict__ Wrls,
                                              const int* __restrict__ sep)
{
    double* A = (double*)dynsmem;
    double* Bv = A + 129 * 130;
    int tid = threadIdx.x;
    if (sep[0] == 0) {
        for (int i = tid; i < 1290; i += 256) g_W[i] = Wrls[i];
        return;
    }
    for (int i = tid; i < 16641; i += 256) A[(i / 129) * 130 + (i % 129)] = g_A[i];
    for (int i = tid; i < 1290; i += 256) Bv[i] = g_Bm[i];
    __syncthreads();
    __shared__ double sinv;
    for (int k = 0; k < 129; k++) {
        if (tid == 0) {
            double d = sqrt(A[k * 130 + k]);
            A[k * 130 + k] = d;
            sinv = 1.0 / d;
        }
        __syncthreads();
        double iv = sinv;
        for (int i = k + 1 + tid; i < 129; i += 256) A[i * 130 + k] *= iv;
        __syncthreads();
        int m = 128 - k;
        for (int t = tid; t < m * m; t += 256) {
            int i = k + 1 + t / m, j = k + 1 + t % m;
            A[i * 130 + j] -= A[i * 130 + k] * A[j * 130 + k];
        }
        __syncthreads();
    }
    for (int k = 0; k < 129; k++) {
        if (tid < 10) Bv[k * 10 + tid] /= A[k * 130 + k];
        __syncthreads();
        for (int t = tid; t < (128 - k) * 10; t += 256) {
            int i = k + 1 + t / 10, c = t % 10;
            Bv[i * 10 + c] -= A[i * 130 + k] * Bv[k * 10 + c];
        }
        __syncthreads();
    }
    for (int k = 128; k >= 0; k--) {
        if (tid < 10) Bv[k * 10 + tid] /= A[k * 130 + k];
        __syncthreads();
        for (int t = tid; t < k * 10; t += 256) {
            int i = t / 10, c = t % 10;
            Bv[i * 10 + c] -= A[k * 130 + i] * Bv[k * 10 + c];
        }
        __syncthreads();
    }
    for (int i = tid; i < 1290; i += 256) g_W[i] = (float)Bv[i];
}

// ===== head =====
__global__ __launch_bounds__(256) void k_head(float* __restrict__ out)
{
    __shared__ float sW[1290];
    int tid = threadIdx.x;
    for (int i = tid; i < 1290; i += 256) sW[i] = g_W[i];
    __syncthreads();
    int idx = blockIdx.x * 256 + tid;
    if (idx >= NB * 10) return;
    int n = idx / 10, c = idx % 10;
    float acc = sW[1280 + c];
    const float* f = g_feat + n * 128;
#pragma unroll 8
    for (int i = 0; i < 128; i++) acc = fmaf(f[i], sW[i * 10 + c], acc);
    out[idx] = acc;
}

extern "C" void kernel_launch(void* const* d_in, const int* in_sizes, int n_in,
                              void* d_out, int out_size)
{
    const float* x       = (const float*)d_in[0];
    const float* y       = (const float*)d_in[1];
    const float* conv1_w = (const float*)d_in[2];
    const float* conv1_b = (const float*)d_in[3];
    const float* bn1_g   = (const float*)d_in[4];
    const float* bn1_b   = (const float*)d_in[5];
    const float* conv2_w = (const float*)d_in[6];
    const float* conv2_b = (const float*)d_in[7];
    const float* bn2_g   = (const float*)d_in[8];
    const float* bn2_b   = (const float*)d_in[9];
    const float* fc1_w   = (const float*)d_in[10];
    const float* fc1_b   = (const float*)d_in[11];
    const float* W_rls   = (const float*)d_in[12];
    const int*   sep     = (const int*)d_in[14];
    float* out = (float*)d_out;

    cudaFuncSetAttribute(k_conv2, cudaFuncAttributeMaxDynamicSharedMemorySize, 106624);
    cudaFuncSetAttribute(k_chol, cudaFuncAttributeMaxDynamicSharedMemorySize, 144480);

    float* p1; cudaGetSymbolAddress((void**)&p1, g_part1);
    float* p2; cudaGetSymbolAddress((void**)&p2, g_part2);
    float* b1; cudaGetSymbolAddress((void**)&b1, g_bn1);
    float* b2; cudaGetSymbolAddress((void**)&b2, g_bn2);

    k_conv1_stats<<<NB, 256>>>(x, conv1_w, conv1_b);
    k_bnfinal<<<32, 256>>>(bn1_g, bn1_b, p1, b1, 32, 1.f / (float)(NB * 784));
    k_conv1_pool<<<NB, 256>>>(x, conv1_w, conv1_b);
    k_conv2<<<NB, 448, 106624>>>(conv2_w, conv2_b);
    k_bnfinal<<<64, 256>>>(bn2_g, bn2_b, p2, b2, 64, 1.f / (float)(NB * 196));
    k_fc1<<<dim3(64, 8), 256>>>(fc1_w);
    k_fc1combine<<<(NB * 128) / 256, 256>>>(fc1_b);
    k_syrk<<<dim3(5, 5, 64), 256>>>();
    k_reduceA<<<66, 256>>>();
    k_phity<<<64, 256>>>(y);
    k_Bfinal<<<6, 256>>>(W_rls);
    k_chol<<<1, 256, 144480>>>(W_rls, sep);
    k_head<<<(NB * 10 + 255) / 256, 256>>>(out);
}

// round 5
// speedup vs baseline: 1.5769x; 1.2338x over previous
#include <cuda_runtime.h>
#include <math.h>

#define NB 4096

// ----- scratch (device globals; no allocations) -----
__device__ float  g_h1max[NB * 32 * 196];
__device__ float  g_h1min[NB * 32 * 196];
__device__ float  g_out2[NB * 64 * 196];
__device__ float  g_feat[NB * 128];
__device__ float  g_part1[NB * 64];
__device__ float  g_part2[NB * 128];
__device__ float  g_bn1[64];
__device__ float  g_bn2[128];
__device__ float  g_fcpart[8 * NB * 128];
__device__ float  g_partA[64 * 129 * 129];
__device__ float  g_partB[64 * 1290];
__device__ double g_A[129 * 129];
__device__ double g_Bm[1290];
__device__ float  g_W[1290];

extern __shared__ char dynsmem[];

// ===== conv1 single pass: raw-conv window max/min + BN stats =====
// One block = one image, 224 threads, one 2x2 pool window per thread (196 used).
// pool(relu(BN(v))) == relu(sc*max+sh) if sc>=0 else relu(sc*min+sh)  (monotone)
__global__ __launch_bounds__(224) void k_conv1_mmx(
    const float* __restrict__ x, const float* __restrict__ w, const float* __restrict__ bias)
{
    __shared__ float simg[900], sw[288], sb[32], wred[7][64];
    int n = blockIdx.x, tid = threadIdx.x;
    for (int i = tid; i < 900; i += 224) simg[i] = 0.f;
    for (int i = tid; i < 288; i += 224) sw[i] = w[i];
    if (tid < 32) sb[tid] = bias[tid];
    __syncthreads();
    const float* xi = x + n * 784;
    for (int i = tid; i < 784; i += 224)
        simg[(i / 28 + 1) * 30 + (i % 28) + 1] = xi[i];
    __syncthreads();

    float ls[32], lq[32];
#pragma unroll
    for (int c = 0; c < 32; c++) { ls[c] = 0.f; lq[c] = 0.f; }

    if (tid < 196) {
        int py = tid / 14, px = tid % 14;
        float patch[16];
#pragma unroll
        for (int dy = 0; dy < 4; dy++)
#pragma unroll
            for (int dx = 0; dx < 4; dx++)
                patch[dy * 4 + dx] = simg[(2 * py + dy) * 30 + 2 * px + dx];
#pragma unroll
        for (int oc = 0; oc < 32; oc++) {
            float v[4];
#pragma unroll
            for (int dy = 0; dy < 2; dy++)
#pragma unroll
                for (int dx = 0; dx < 2; dx++) {
                    float a = sb[oc];
#pragma unroll
                    for (int ky = 0; ky < 3; ky++)
#pragma unroll
                        for (int kx = 0; kx < 3; kx++)
                            a = fmaf(sw[oc * 9 + ky * 3 + kx],
                                     patch[(dy + ky) * 4 + dx + kx], a);
                    v[dy * 2 + dx] = a;
                }
            float mx = fmaxf(fmaxf(v[0], v[1]), fmaxf(v[2], v[3]));
            float mn = fminf(fminf(v[0], v[1]), fminf(v[2], v[3]));
            g_h1max[(n * 32 + oc) * 196 + tid] = mx;
            g_h1min[(n * 32 + oc) * 196 + tid] = mn;
            ls[oc] += (v[0] + v[1]) + (v[2] + v[3]);
            lq[oc] = fmaf(v[0], v[0], fmaf(v[1], v[1], fmaf(v[2], v[2], fmaf(v[3], v[3], lq[oc]))));
        }
    }
    int lane = tid & 31, wid = tid >> 5;
#pragma unroll
    for (int oc = 0; oc < 32; oc++) {
        float s = ls[oc], q = lq[oc];
#pragma unroll
        for (int o = 16; o > 0; o >>= 1) {
            s += __shfl_down_sync(0xffffffffu, s, o);
            q += __shfl_down_sync(0xffffffffu, q, o);
        }
        if (lane == 0) { wred[wid][oc] = s; wred[wid][32 + oc] = q; }
    }
    __syncthreads();
    if (tid < 64) {
        float s = 0.f;
#pragma unroll
        for (int w7 = 0; w7 < 7; w7++) s += wred[w7][tid];
        g_part1[n * 64 + tid] = s;
    }
}

// ===== BN finalize =====
__global__ __launch_bounds__(256) void k_bnfinal(
    const float* __restrict__ gamma, const float* __restrict__ beta,
    const float* __restrict__ part, float* __restrict__ bn, int nc, float invN)
{
    int c = blockIdx.x, tid = threadIdx.x;
    float s = 0.f, q = 0.f;
    for (int r = tid; r < NB; r += 256) {
        s += part[r * 2 * nc + c];
        q += part[r * 2 * nc + nc + c];
    }
    __shared__ float ss[256], sq[256];
    ss[tid] = s; sq[tid] = q; __syncthreads();
    for (int o = 128; o > 0; o >>= 1) {
        if (tid < o) { ss[tid] += ss[tid + o]; sq[tid] += sq[tid + o]; }
        __syncthreads();
    }
    if (tid == 0) {
        float mean = ss[0] * invN;
        float var = sq[0] * invN - mean * mean;
        float scale = gamma[c] * rsqrtf(var + 1e-5f);
        bn[c] = scale;
        bn[nc + c] = beta[c] - mean * scale;
    }
}

// ===== conv2 (scalar R3 core) + inline BN1/relu/pool on input load =====
// 448 thr: slot = oy*32 + ocp. Warp-uniform input rows (broadcasts),
// weight rows padded to stride 577 (577 mod 32 == 1) -> conflict-free.
__global__ __launch_bounds__(448, 2) void k_conv2(
    const float* __restrict__ cw, const float* __restrict__ cb)
{
    float* sw2 = (float*)dynsmem;            // 32 * 577
    float* sin = sw2 + 18464;                // 32 ch * 256 (16x16 zero-padded)
    __shared__ float ssc1[32], ssh1[32];
    int n = blockIdx.x, tid = threadIdx.x;
    for (int i = tid; i < 18432; i += 448) {
        int oc = i / 288, r = i % 288;
        sw2[(oc >> 1) * 577 + (oc & 1) * 288 + r] = cw[i];
    }
    for (int i = tid; i < 8192; i += 448) sin[i] = 0.f;
    if (tid < 32) { ssc1[tid] = g_bn1[tid]; ssh1[tid] = g_bn1[32 + tid]; }
    __syncthreads();
    const float* mxp = g_h1max + n * 6272;
    const float* mnp = g_h1min + n * 6272;
    for (int i = tid; i < 6272; i += 448) {
        int ci = i / 196, p = i % 196;
        float sc = ssc1[ci], sh = ssh1[ci];
        float base = (sc >= 0.f) ? mxp[i] : mnp[i];
        sin[ci * 256 + (p / 14 + 1) * 16 + (p % 14 + 1)] = fmaxf(fmaf(sc, base, sh), 0.f);
    }
    __syncthreads();

    float* op = g_out2 + n * 12544;
    int oy = tid >> 5, ocp = tid & 31;

    float a0[14], a1[14];
#pragma unroll
    for (int xx = 0; xx < 14; xx++) { a0[xx] = 0.f; a1[xx] = 0.f; }
    const float* wb0 = sw2 + ocp * 577;
    const float* wb1 = wb0 + 288;
    for (int ci = 0; ci < 32; ci++) {
        const float* ip = sin + ci * 256 + oy * 16;
        const float* w0p = wb0 + ci * 9;
        const float* w1p = wb1 + ci * 9;
#pragma unroll
        for (int ky = 0; ky < 3; ky++) {
            float rr[16];
#pragma unroll
            for (int j = 0; j < 16; j++) rr[j] = ip[ky * 16 + j];
#pragma unroll
            for (int kx = 0; kx < 3; kx++) {
                float w0 = w0p[ky * 3 + kx], w1 = w1p[ky * 3 + kx];
#pragma unroll
                for (int xx = 0; xx < 14; xx++) {
                    a0[xx] = fmaf(rr[xx + kx], w0, a0[xx]);
                    a1[xx] = fmaf(rr[xx + kx], w1, a1[xx]);
                }
            }
        }
    }
    int oc0 = 2 * ocp;
    float b0 = cb[oc0], b1 = cb[oc0 + 1];
    float s0 = 0.f, q0 = 0.f, s1 = 0.f, q1 = 0.f;
#pragma unroll
    for (int xx = 0; xx < 14; xx++) {
        float v0 = a0[xx] + b0, v1 = a1[xx] + b1;
        op[(oc0 * 14 + oy) * 14 + xx] = v0;
        op[((oc0 + 1) * 14 + oy) * 14 + xx] = v1;
        s0 += v0; q0 = fmaf(v0, v0, q0);
        s1 += v1; q1 = fmaf(v1, v1, q1);
    }
    __syncthreads();
    float* sred = sin;
    sred[tid * 4 + 0] = s0; sred[tid * 4 + 1] = q0;
    sred[tid * 4 + 2] = s1; sred[tid * 4 + 3] = q1;
    __syncthreads();
    if (tid < 64) {
        int p = tid >> 1, h = tid & 1;
        float s = 0.f, q = 0.f;
        for (int r = 0; r < 14; r++) {
            int si = r * 32 + p;
            s += sred[si * 4 + h * 2 + 0];
            q += sred[si * 4 + h * 2 + 1];
        }
        g_part2[n * 128 + tid] = s;
        g_part2[n * 128 + 64 + tid] = q;
    }
}

// ===== fc1 (BN2+relu+pool fused into the A-tile load) =====
__global__ __launch_bounds__(256) void k_fc1(const float* __restrict__ fw)
{
    __shared__ float As[32][65], Bs[32][130];
    int m0 = blockIdx.x * 64, z = blockIdx.y;
    int kt0 = ((98 * z) / 8) * 32, kt1 = ((98 * (z + 1)) / 8) * 32;
    int tid = threadIdx.x, tx = tid & 31, ty = tid >> 5;
    float acc[8][4];
#pragma unroll
    for (int u = 0; u < 8; u++)
#pragma unroll
        for (int v = 0; v < 4; v++) acc[u][v] = 0.f;
    for (int k0 = kt0; k0 < kt1; k0 += 32) {
        for (int i = tid; i < 2048; i += 256) {
            int r = i >> 5, c = i & 31;
            int kk = k0 + c;
            int oc = kk / 49, p = kk - oc * 49, py = p / 7, px = p - py * 7;
            const float* base = g_out2 + ((m0 + r) * 64 + oc) * 196 + 2 * py * 14 + 2 * px;
            float sc = __ldg(&g_bn2[oc]), sh = __ldg(&g_bn2[64 + oc]);
            float v = fmaxf(fmaf(sc, base[0], sh), 0.f);
            v = fmaxf(v, fmaxf(fmaf(sc, base[1], sh), 0.f));
            v = fmaxf(v, fmaxf(fmaf(sc, base[14], sh), 0.f));
            v = fmaxf(v, fmaxf(fmaf(sc, base[15], sh), 0.f));
            As[c][r] = v;
        }
        for (int i = tid; i < 4096; i += 256) {
            int r = i >> 5, c = i & 31;
            Bs[c][r] = fw[r * 3136 + k0 + c];
        }
        __syncthreads();
#pragma unroll
        for (int k = 0; k < 32; k++) {
            float a[8], b[4];
#pragma unroll
            for (int u = 0; u < 8; u++) a[u] = As[k][ty * 8 + u];
#pragma unroll
            for (int v = 0; v < 4; v++) b[v] = Bs[k][tx * 4 + v];
#pragma unroll
            for (int u = 0; u < 8; u++)
#pragma unroll
                for (int v = 0; v < 4; v++) acc[u][v] = fmaf(a[u], b[v], acc[u][v]);
        }
        __syncthreads();
    }
    float* pp = g_fcpart + z * (NB * 128);
#pragma unroll
    for (int u = 0; u < 8; u++)
#pragma unroll
        for (int v = 0; v < 4; v++)
            pp[(m0 + ty * 8 + u) * 128 + tx * 4 + v] = acc[u][v];
}

__global__ __launch_bounds__(256) void k_fc1combine(const float* __restrict__ fb)
{
    int idx = blockIdx.x * 256 + threadIdx.x;
    if (idx >= NB * 128) return;
    float v = fb[idx & 127];
#pragma unroll
    for (int z = 0; z < 8; z++) v += g_fcpart[z * (NB * 128) + idx];
    g_feat[idx] = fmaxf(v, 0.f);
}

// ===== SYRK chunk partials =====
__global__ __launch_bounds__(256) void k_syrk()
{
    __shared__ float As[64][33], Bs[64][33];
    int ti = blockIdx.x, tj = blockIdx.y, ch = blockIdx.z;
    int tid = threadIdx.x, tx = tid & 15, ty = tid >> 4, n0 = ch * 64;
    for (int i = tid; i < 2048; i += 256) {
        int r = i >> 5, c = i & 31;
        int gi = ti * 32 + c, gj = tj * 32 + c;
        As[r][c] = (gi < 128) ? g_feat[(n0 + r) * 128 + gi] : (gi == 128 ? 1.f : 0.f);
        Bs[r][c] = (gj < 128) ? g_feat[(n0 + r) * 128 + gj] : (gj == 128 ? 1.f : 0.f);
    }
    __syncthreads();
    float a00 = 0.f, a01 = 0.f, a10 = 0.f, a11 = 0.f;
#pragma unroll 8
    for (int k = 0; k < 64; k++) {
        float x0 = As[k][2 * ty], x1 = As[k][2 * ty + 1];
        float y0 = Bs[k][2 * tx], y1 = Bs[k][2 * tx + 1];
        a00 = fmaf(x0, y0, a00); a01 = fmaf(x0, y1, a01);
        a10 = fmaf(x1, y0, a10); a11 = fmaf(x1, y1, a11);
    }
    float* pa = g_partA + ch * 16641;
    int gi0 = ti * 32 + 2 * ty, gj0 = tj * 32 + 2 * tx;
    if (gi0 < 129 && gj0 < 129) pa[gi0 * 129 + gj0] = a00;
    if (gi0 < 129 && gj0 + 1 < 129) pa[gi0 * 129 + gj0 + 1] = a01;
    if (gi0 + 1 < 129 && gj0 < 129) pa[(gi0 + 1) * 129 + gj0] = a10;
    if (gi0 + 1 < 129 && gj0 + 1 < 129) pa[(gi0 + 1) * 129 + gj0 + 1] = a11;
}

__global__ __launch_bounds__(256) void k_reduceA()
{
    int o = blockIdx.x * 256 + threadIdx.x;
    if (o >= 16641) return;
    double s = ((o / 129) == (o % 129)) ? 1.0 : 0.0;
    for (int ch = 0; ch < 64; ch++) s += (double)g_partA[ch * 16641 + o];
    g_A[o] = s;
}

// ===== Phi^T Y chunk partials =====
__global__ __launch_bounds__(256) void k_phity(const float* __restrict__ y)
{
    __shared__ float sf[64 * 129], sy[640];
    int ch = blockIdx.x, n0 = ch * 64, tid = threadIdx.x;
    for (int i = tid; i < 8192; i += 256)
        sf[(i >> 7) * 129 + (i & 127)] = g_feat[(n0 + (i >> 7)) * 128 + (i & 127)];
    for (int i = tid; i < 64; i += 256) sf[i * 129 + 128] = 1.f;
    for (int i = tid; i < 640; i += 256) sy[i] = y[n0 * 10 + i];
    __syncthreads();
    for (int o = tid; o < 1290; o += 256) {
        int i = o / 10, c = o % 10;
        float s = 0.f;
        for (int r = 0; r < 64; r++) s = fmaf(sf[r * 129 + i], sy[r * 10 + c], s);
        g_partB[ch * 1290 + o] = s;
    }
}

__global__ __launch_bounds__(256) void k_Bfinal(const float* __restrict__ Wrls)
{
    int o = blockIdx.x * 256 + threadIdx.x;
    if (o >= 1290) return;
    double s = (double)Wrls[o];
    for (int ch = 0; ch < 64; ch++) s += (double)g_partB[ch * 1290 + o];
    g_Bm[o] = s;
}

// ===== fp64 Cholesky + 10-RHS solve =====
__global__ __launch_bounds__(256) void k_chol(const float* __restrict__ Wrls,
                                              const int* __restrict__ sep)
{
    double* A = (double*)dynsmem;
    double* Bv = A + 129 * 130;
    int tid = threadIdx.x;
    if (sep[0] == 0) {
        for (int i = tid; i < 1290; i += 256) g_W[i] = Wrls[i];
        return;
    }
    for (int i = tid; i < 16641; i += 256) A[(i / 129) * 130 + (i % 129)] = g_A[i];
    for (int i = tid; i < 1290; i += 256) Bv[i] = g_Bm[i];
    __syncthreads();
    __shared__ double sinv;
    for (int k = 0; k < 129; k++) {
        if (tid == 0) {
            double d = sqrt(A[k * 130 + k]);
            A[k * 130 + k] = d;
            sinv = 1.0 / d;
        }
        __syncthreads();
        double iv = sinv;
        for (int i = k + 1 + tid; i < 129; i += 256) A[i * 130 + k] *= iv;
        __syncthreads();
        int m = 128 - k;
        for (int t = tid; t < m * m; t += 256) {
            int i = k + 1 + t / m, j = k + 1 + t % m;
            A[i * 130 + j] -= A[i * 130 + k] * A[j * 130 + k];
        }
        __syncthreads();
    }
    for (int k = 0; k < 129; k++) {
        if (tid < 10) Bv[k * 10 + tid] /= A[k * 130 + k];
        __syncthreads();
        for (int t = tid; t < (128 - k) * 10; t += 256) {
            int i = k + 1 + t / 10, c = t % 10;
            Bv[i * 10 + c] -= A[i * 130 + k] * Bv[k * 10 + c];
        }
        __syncthreads();
    }
    for (int k = 128; k >= 0; k--) {
        if (tid < 10) Bv[k * 10 + tid] /= A[k * 130 + k];
        __syncthreads();
        for (int t = tid; t < k * 10; t += 256) {
            int i = t / 10, c = t % 10;
            Bv[i * 10 + c] -= A[k * 130 + i] * Bv[k * 10 + c];
        }
        __syncthreads();
    }
    for (int i = tid; i < 1290; i += 256) g_W[i] = (float)Bv[i];
}

// ===== head =====
__global__ __launch_bounds__(256) void k_head(float* __restrict__ out)
{
    __shared__ float sW[1290];
    int tid = threadIdx.x;
    for (int i = tid; i < 1290; i += 256) sW[i] = g_W[i];
    __syncthreads();
    int idx = blockIdx.x * 256 + tid;
    if (idx >= NB * 10) return;
    int n = idx / 10, c = idx % 10;
    float acc = sW[1280 + c];
    const float* f = g_feat + n * 128;
#pragma unroll 8
    for (int i = 0; i < 128; i++) acc = fmaf(f[i], sW[i * 10 + c], acc);
    out[idx] = acc;
}

extern "C" void kernel_launch(void* const* d_in, const int* in_sizes, int n_in,
                              void* d_out, int out_size)
{
    const float* x       = (const float*)d_in[0];
    const float* y       = (const float*)d_in[1];
    const float* conv1_w = (const float*)d_in[2];
    const float* conv1_b = (const float*)d_in[3];
    const float* bn1_g   = (const float*)d_in[4];
    const float* bn1_b   = (const float*)d_in[5];
    const float* conv2_w = (const float*)d_in[6];
    const float* conv2_b = (const float*)d_in[7];
    const float* bn2_g   = (const float*)d_in[8];
    const float* bn2_b   = (const float*)d_in[9];
    const float* fc1_w   = (const float*)d_in[10];
    const float* fc1_b   = (const float*)d_in[11];
    const float* W_rls   = (const float*)d_in[12];
    const int*   sep     = (const int*)d_in[14];
    float* out = (float*)d_out;

    cudaFuncSetAttribute(k_conv2, cudaFuncAttributeMaxDynamicSharedMemorySize, 106624);
    cudaFuncSetAttribute(k_chol, cudaFuncAttributeMaxDynamicSharedMemorySize, 144480);

    float* p1; cudaGetSymbolAddress((void**)&p1, g_part1);
    float* p2; cudaGetSymbolAddress((void**)&p2, g_part2);
    float* b1; cudaGetSymbolAddress((void**)&b1, g_bn1);
    float* b2; cudaGetSymbolAddress((void**)&b2, g_bn2);

    k_conv1_mmx<<<NB, 224>>>(x, conv1_w, conv1_b);
    k_bnfinal<<<32, 256>>>(bn1_g, bn1_b, p1, b1, 32, 1.f / (float)(NB * 784));
    k_conv2<<<NB, 448, 106624>>>(conv2_w, conv2_b);
    k_bnfinal<<<64, 256>>>(bn2_g, bn2_b, p2, b2, 64, 1.f / (float)(NB * 196));
    k_fc1<<<dim3(64, 8), 256>>>(fc1_w);
    k_fc1combine<<<(NB * 128) / 256, 256>>>(fc1_b);
    k_syrk<<<dim3(5, 5, 64), 256>>>();
    k_reduceA<<<66, 256>>>();
    k_phity<<<64, 256>>>(y);
    k_Bfinal<<<6, 256>>>(W_rls);
    k_chol<<<1, 256, 144480>>>(W_rls, sep);
    k_head<<<(NB * 10 + 255) / 256, 256>>>(out);
}

// round 6
// speedup vs baseline: 1.7364x; 1.1012x over previous
#include <cuda_runtime.h>
#include <math.h>

#define NB 4096

// ----- scratch (device globals; no allocations) -----
__device__ float  g_h1max[NB * 32 * 196];
__device__ float  g_h1min[NB * 32 * 196];
__device__ float  g_o2max[NB * 64 * 49];
__device__ float  g_o2min[NB * 64 * 49];
__device__ float  g_feat[NB * 128];
__device__ float  g_part1[NB * 64];
__device__ float  g_part2[NB * 128];
__device__ float  g_bn1[64];
__device__ float  g_bn2[128];
__device__ float  g_fcpart[8 * NB * 128];
__device__ float  g_partA[64 * 129 * 129];
__device__ float  g_partB[64 * 1290];
__device__ double g_A[129 * 129];
__device__ double g_Bm[1290];
__device__ float  g_W[1290];

extern __shared__ char dynsmem[];

// ===== conv1 single pass: raw-conv window max/min + BN stats =====
__global__ __launch_bounds__(224) void k_conv1_mmx(
    const float* __restrict__ x, const float* __restrict__ w, const float* __restrict__ bias)
{
    __shared__ float simg[900], sw[288], sb[32], wred[7][64];
    int n = blockIdx.x, tid = threadIdx.x;
    for (int i = tid; i < 900; i += 224) simg[i] = 0.f;
    for (int i = tid; i < 288; i += 224) sw[i] = w[i];
    if (tid < 32) sb[tid] = bias[tid];
    __syncthreads();
    const float* xi = x + n * 784;
    for (int i = tid; i < 784; i += 224)
        simg[(i / 28 + 1) * 30 + (i % 28) + 1] = xi[i];
    __syncthreads();

    float ls[32], lq[32];
#pragma unroll
    for (int c = 0; c < 32; c++) { ls[c] = 0.f; lq[c] = 0.f; }

    if (tid < 196) {
        int py = tid / 14, px = tid % 14;
        float patch[16];
#pragma unroll
        for (int dy = 0; dy < 4; dy++)
#pragma unroll
            for (int dx = 0; dx < 4; dx++)
                patch[dy * 4 + dx] = simg[(2 * py + dy) * 30 + 2 * px + dx];
#pragma unroll
        for (int oc = 0; oc < 32; oc++) {
            float v[4];
#pragma unroll
            for (int dy = 0; dy < 2; dy++)
#pragma unroll
                for (int dx = 0; dx < 2; dx++) {
                    float a = sb[oc];
#pragma unroll
                    for (int ky = 0; ky < 3; ky++)
#pragma unroll
                        for (int kx = 0; kx < 3; kx++)
                            a = fmaf(sw[oc * 9 + ky * 3 + kx],
                                     patch[(dy + ky) * 4 + dx + kx], a);
                    v[dy * 2 + dx] = a;
                }
            float mx = fmaxf(fmaxf(v[0], v[1]), fmaxf(v[2], v[3]));
            float mn = fminf(fminf(v[0], v[1]), fminf(v[2], v[3]));
            g_h1max[(n * 32 + oc) * 196 + tid] = mx;
            g_h1min[(n * 32 + oc) * 196 + tid] = mn;
            ls[oc] += (v[0] + v[1]) + (v[2] + v[3]);
            lq[oc] = fmaf(v[0], v[0], fmaf(v[1], v[1], fmaf(v[2], v[2], fmaf(v[3], v[3], lq[oc]))));
        }
    }
    int lane = tid & 31, wid = tid >> 5;
#pragma unroll
    for (int oc = 0; oc < 32; oc++) {
        float s = ls[oc], q = lq[oc];
#pragma unroll
        for (int o = 16; o > 0; o >>= 1) {
            s += __shfl_down_sync(0xffffffffu, s, o);
            q += __shfl_down_sync(0xffffffffu, q, o);
        }
        if (lane == 0) { wred[wid][oc] = s; wred[wid][32 + oc] = q; }
    }
    __syncthreads();
    if (tid < 64) {
        float s = 0.f;
#pragma unroll
        for (int w7 = 0; w7 < 7; w7++) s += wred[w7][tid];
        g_part1[n * 64 + tid] = s;
    }
}

// ===== BN finalize =====
__global__ __launch_bounds__(256) void k_bnfinal(
    const float* __restrict__ gamma, const float* __restrict__ beta,
    const float* __restrict__ part, float* __restrict__ bn, int nc, float invN)
{
    int c = blockIdx.x, tid = threadIdx.x;
    float s = 0.f, q = 0.f;
    for (int r = tid; r < NB; r += 256) {
        s += part[r * 2 * nc + c];
        q += part[r * 2 * nc + nc + c];
    }
    __shared__ float ss[256], sq[256];
    ss[tid] = s; sq[tid] = q; __syncthreads();
    for (int o = 128; o > 0; o >>= 1) {
        if (tid < o) { ss[tid] += ss[tid + o]; sq[tid] += sq[tid + o]; }
        __syncthreads();
    }
    if (tid == 0) {
        float mean = ss[0] * invN;
        float var = sq[0] * invN - mean * mean;
        float scale = gamma[c] * rsqrtf(var + 1e-5f);
        bn[c] = scale;
        bn[nc + c] = beta[c] - mean * scale;
    }
}

// ===== conv2: scalar core + inline BN1 select + pooled (max,min) output =====
__global__ __launch_bounds__(448, 2) void k_conv2(
    const float* __restrict__ cw, const float* __restrict__ cb)
{
    float* sw2 = (float*)dynsmem;            // 32 * 577
    float* sin = sw2 + 18464;                // 32 ch * 256 (16x16 zero-padded)
    __shared__ float ssc1[32], ssh1[32];
    int n = blockIdx.x, tid = threadIdx.x;
    for (int i = tid; i < 18432; i += 448) {
        int oc = i / 288, r = i % 288;
        sw2[(oc >> 1) * 577 + (oc & 1) * 288 + r] = cw[i];
    }
    for (int i = tid; i < 8192; i += 448) sin[i] = 0.f;
    if (tid < 32) { ssc1[tid] = g_bn1[tid]; ssh1[tid] = g_bn1[32 + tid]; }
    __syncthreads();
    const float* mxp = g_h1max + n * 6272;
    const float* mnp = g_h1min + n * 6272;
    for (int i = tid; i < 6272; i += 448) {
        int ci = i / 196, p = i % 196;
        float sc = ssc1[ci], sh = ssh1[ci];
        float base = (sc >= 0.f) ? mxp[i] : mnp[i];
        sin[ci * 256 + (p / 14 + 1) * 16 + (p % 14 + 1)] = fmaxf(fmaf(sc, base, sh), 0.f);
    }
    __syncthreads();

    int oy = tid >> 5, ocp = tid & 31;

    float a0[14], a1[14];
#pragma unroll
    for (int xx = 0; xx < 14; xx++) { a0[xx] = 0.f; a1[xx] = 0.f; }
    const float* wb0 = sw2 + ocp * 577;
    const float* wb1 = wb0 + 288;
    for (int ci = 0; ci < 32; ci++) {
        const float* ip = sin + ci * 256 + oy * 16;
        const float* w0p = wb0 + ci * 9;
        const float* w1p = wb1 + ci * 9;
#pragma unroll
        for (int ky = 0; ky < 3; ky++) {
            float rr[16];
#pragma unroll
            for (int j = 0; j < 16; j++) rr[j] = ip[ky * 16 + j];
#pragma unroll
            for (int kx = 0; kx < 3; kx++) {
                float w0 = w0p[ky * 3 + kx], w1 = w1p[ky * 3 + kx];
#pragma unroll
                for (int xx = 0; xx < 14; xx++) {
                    a0[xx] = fmaf(rr[xx + kx], w0, a0[xx]);
                    a1[xx] = fmaf(rr[xx + kx], w1, a1[xx]);
                }
            }
        }
    }
    int oc0 = 2 * ocp;
    float b0 = cb[oc0], b1 = cb[oc0 + 1];
    float s0 = 0.f, q0 = 0.f, s1 = 0.f, q1 = 0.f;
#pragma unroll
    for (int xx = 0; xx < 14; xx++) {
        a0[xx] += b0; a1[xx] += b1;
        s0 += a0[xx]; q0 = fmaf(a0[xx], a0[xx], q0);
        s1 += a1[xx]; q1 = fmaf(a1[xx], a1[xx], q1);
    }
    __syncthreads();                          // all smem reads done -> reuse
    float* ex = (float*)dynsmem;              // 448 rows * 29 (stride 29: conflict-free)
    float* sred = ex + 12992;                 // 448 * 4
    float* row = ex + tid * 29;
#pragma unroll
    for (int j = 0; j < 14; j++) { row[j] = a0[j]; row[14 + j] = a1[j]; }
    sred[tid * 4 + 0] = s0; sred[tid * 4 + 1] = q0;
    sred[tid * 4 + 2] = s1; sred[tid * 4 + 3] = q1;
    __syncthreads();
    if (tid < 224) {                          // pooled max/min: 2 oc x 7 px each
        int py = tid >> 5, p2 = tid & 31;
        const float* r0 = ex + ((2 * py) * 32 + p2) * 29;
        const float* r1 = ex + ((2 * py + 1) * 32 + p2) * 29;
#pragma unroll
        for (int h = 0; h < 2; h++) {
            int ob = (n * 64 + 2 * p2 + h) * 49 + py * 7;
#pragma unroll
            for (int px = 0; px < 7; px++) {
                float u0 = r0[h * 14 + 2 * px], u1 = r0[h * 14 + 2 * px + 1];
                float u2 = r1[h * 14 + 2 * px], u3 = r1[h * 14 + 2 * px + 1];
                g_o2max[ob + px] = fmaxf(fmaxf(u0, u1), fmaxf(u2, u3));
                g_o2min[ob + px] = fminf(fminf(u0, u1), fminf(u2, u3));
            }
        }
    }
    if (tid < 64) {
        int p = tid >> 1, h = tid & 1;
        float s = 0.f, q = 0.f;
        for (int r = 0; r < 14; r++) {
            int si = r * 32 + p;
            s += sred[si * 4 + h * 2 + 0];
            q += sred[si * 4 + h * 2 + 1];
        }
        g_part2[n * 128 + tid] = s;
        g_part2[n * 128 + 64 + tid] = q;
    }
}

// ===== fc1 (BN2 select on pooled arrays; coalesced) =====
__global__ __launch_bounds__(256) void k_fc1(const float* __restrict__ fw)
{
    __shared__ float As[32][65], Bs[32][130];
    int m0 = blockIdx.x * 64, z = blockIdx.y;
    int kt0 = ((98 * z) / 8) * 32, kt1 = ((98 * (z + 1)) / 8) * 32;
    int tid = threadIdx.x, tx = tid & 31, ty = tid >> 5;
    float acc[8][4];
#pragma unroll
    for (int u = 0; u < 8; u++)
#pragma unroll
        for (int v = 0; v < 4; v++) acc[u][v] = 0.f;
    for (int k0 = kt0; k0 < kt1; k0 += 32) {
        for (int i = tid; i < 2048; i += 256) {
            int r = i >> 5, c = i & 31;
            int kk = k0 + c;
            int oc = kk / 49, p = kk - oc * 49;
            float sc = __ldg(&g_bn2[oc]), sh = __ldg(&g_bn2[64 + oc]);
            int off = ((m0 + r) * 64 + oc) * 49 + p;
            float base = (sc >= 0.f) ? g_o2max[off] : g_o2min[off];
            As[c][r] = fmaxf(fmaf(sc, base, sh), 0.f);
        }
        for (int i = tid; i < 4096; i += 256) {
            int r = i >> 5, c = i & 31;
            Bs[c][r] = fw[r * 3136 + k0 + c];
        }
        __syncthreads();
#pragma unroll
        for (int k = 0; k < 32; k++) {
            float a[8], b[4];
#pragma unroll
            for (int u = 0; u < 8; u++) a[u] = As[k][ty * 8 + u];
#pragma unroll
            for (int v = 0; v < 4; v++) b[v] = Bs[k][tx * 4 + v];
#pragma unroll
            for (int u = 0; u < 8; u++)
#pragma unroll
                for (int v = 0; v < 4; v++) acc[u][v] = fmaf(a[u], b[v], acc[u][v]);
        }
        __syncthreads();
    }
    float* pp = g_fcpart + z * (NB * 128);
#pragma unroll
    for (int u = 0; u < 8; u++)
#pragma unroll
        for (int v = 0; v < 4; v++)
            pp[(m0 + ty * 8 + u) * 128 + tx * 4 + v] = acc[u][v];
}

__global__ __launch_bounds__(256) void k_fc1combine(const float* __restrict__ fb)
{
    int idx = blockIdx.x * 256 + threadIdx.x;
    if (idx >= NB * 128) return;
    float v = fb[idx & 127];
#pragma unroll
    for (int z = 0; z < 8; z++) v += g_fcpart[z * (NB * 128) + idx];
    g_feat[idx] = fmaxf(v, 0.f);
}

// ===== SYRK chunk partials =====
__global__ __launch_bounds__(256) void k_syrk()
{
    __shared__ float As[64][33], Bs[64][33];
    int ti = blockIdx.x, tj = blockIdx.y, ch = blockIdx.z;
    int tid = threadIdx.x, tx = tid & 15, ty = tid >> 4, n0 = ch * 64;
    for (int i = tid; i < 2048; i += 256) {
        int r = i >> 5, c = i & 31;
        int gi = ti * 32 + c, gj = tj * 32 + c;
        As[r][c] = (gi < 128) ? g_feat[(n0 + r) * 128 + gi] : (gi == 128 ? 1.f : 0.f);
        Bs[r][c] = (gj < 128) ? g_feat[(n0 + r) * 128 + gj] : (gj == 128 ? 1.f : 0.f);
    }
    __syncthreads();
    float a00 = 0.f, a01 = 0.f, a10 = 0.f, a11 = 0.f;
#pragma unroll 8
    for (int k = 0; k < 64; k++) {
        float x0 = As[k][2 * ty], x1 = As[k][2 * ty + 1];
        float y0 = Bs[k][2 * tx], y1 = Bs[k][2 * tx + 1];
        a00 = fmaf(x0, y0, a00); a01 = fmaf(x0, y1, a01);
        a10 = fmaf(x1, y0, a10); a11 = fmaf(x1, y1, a11);
    }
    float* pa = g_partA + ch * 16641;
    int gi0 = ti * 32 + 2 * ty, gj0 = tj * 32 + 2 * tx;
    if (gi0 < 129 && gj0 < 129) pa[gi0 * 129 + gj0] = a00;
    if (gi0 < 129 && gj0 + 1 < 129) pa[gi0 * 129 + gj0 + 1] = a01;
    if (gi0 + 1 < 129 && gj0 < 129) pa[(gi0 + 1) * 129 + gj0] = a10;
    if (gi0 + 1 < 129 && gj0 + 1 < 129) pa[(gi0 + 1) * 129 + gj0 + 1] = a11;
}

__global__ __launch_bounds__(256) void k_reduceA()
{
    int o = blockIdx.x * 256 + threadIdx.x;
    if (o >= 16641) return;
    double s = ((o / 129) == (o % 129)) ? 1.0 : 0.0;
    for (int ch = 0; ch < 64; ch++) s += (double)g_partA[ch * 16641 + o];
    g_A[o] = s;
}

// ===== Phi^T Y chunk partials =====
__global__ __launch_bounds__(256) void k_phity(const float* __restrict__ y)
{
    __shared__ float sf[64 * 129], sy[640];
    int ch = blockIdx.x, n0 = ch * 64, tid = threadIdx.x;
    for (int i = tid; i < 8192; i += 256)
        sf[(i >> 7) * 129 + (i & 127)] = g_feat[(n0 + (i >> 7)) * 128 + (i & 127)];
    for (int i = tid; i < 64; i += 256) sf[i * 129 + 128] = 1.f;
    for (int i = tid; i < 640; i += 256) sy[i] = y[n0 * 10 + i];
    __syncthreads();
    for (int o = tid; o < 1290; o += 256) {
        int i = o / 10, c = o % 10;
        float s = 0.f;
        for (int r = 0; r < 64; r++) s = fmaf(sf[r * 129 + i], sy[r * 10 + c], s);
        g_partB[ch * 1290 + o] = s;
    }
}

__global__ __launch_bounds__(256) void k_Bfinal(const float* __restrict__ Wrls)
{
    int o = blockIdx.x * 256 + threadIdx.x;
    if (o >= 1290) return;
    double s = (double)Wrls[o];
    for (int ch = 0; ch < 64; ch++) s += (double)g_partB[ch * 1290 + o];
    g_Bm[o] = s;
}

// ===== fp64 Cholesky + 10-RHS solve (lower-triangle updates only) =====
__global__ __launch_bounds__(256) void k_chol(const float* __restrict__ Wrls,
                                              const int* __restrict__ sep)
{
    double* A = (double*)dynsmem;
    double* Bv = A + 129 * 130;
    int tid = threadIdx.x;
    if (sep[0] == 0) {
        for (int i = tid; i < 1290; i += 256) g_W[i] = Wrls[i];
        return;
    }
    for (int i = tid; i < 16641; i += 256) A[(i / 129) * 130 + (i % 129)] = g_A[i];
    for (int i = tid; i < 1290; i += 256) Bv[i] = g_Bm[i];
    __syncthreads();
    __shared__ double sinv;
    for (int k = 0; k < 129; k++) {
        if (tid == 0) {
            double d = sqrt(A[k * 130 + k]);
            A[k * 130 + k] = d;
            sinv = 1.0 / d;
        }
        __syncthreads();
        double iv = sinv;
        for (int i = k + 1 + tid; i < 129; i += 256) A[i * 130 + k] *= iv;
        __syncthreads();
        int m = 128 - k;
        for (int t = tid; t < m * m; t += 256) {
            int i = k + 1 + t / m, j = k + 1 + t % m;
            if (j <= i)
                A[i * 130 + j] -= A[i * 130 + k] * A[j * 130 + k];
        }
        __syncthreads();
    }
    for (int k = 0; k < 129; k++) {
        if (tid < 10) Bv[k * 10 + tid] /= A[k * 130 + k];
        __syncthreads();
        for (int t = tid; t < (128 - k) * 10; t += 256) {
            int i = k + 1 + t / 10, c = t % 10;
            Bv[i * 10 + c] -= A[i * 130 + k] * Bv[k * 10 + c];
        }
        __syncthreads();
    }
    for (int k = 128; k >= 0; k--) {
        if (tid < 10) Bv[k * 10 + tid] /= A[k * 130 + k];
        __syncthreads();
        for (int t = tid; t < k * 10; t += 256) {
            int i = t / 10, c = t % 10;
            Bv[i * 10 + c] -= A[k * 130 + i] * Bv[k * 10 + c];
        }
        __syncthreads();
    }
    for (int i = tid; i < 1290; i += 256) g_W[i] = (float)Bv[i];
}

// ===== head =====
__global__ __launch_bounds__(256) void k_head(float* __restrict__ out)
{
    __shared__ float sW[1290];
    int tid = threadIdx.x;
    for (int i = tid; i < 1290; i += 256) sW[i] = g_W[i];
    __syncthreads();
    int idx = blockIdx.x * 256 + tid;
    if (idx >= NB * 10) return;
    int n = idx / 10, c = idx % 10;
    float acc = sW[1280 + c];
    const float* f = g_feat + n * 128;
#pragma unroll 8
    for (int i = 0; i < 128; i++) acc = fmaf(f[i], sW[i * 10 + c], acc);
    out[idx] = acc;
}

extern "C" void kernel_launch(void* const* d_in, const int* in_sizes, int n_in,
                              void* d_out, int out_size)
{
    const float* x       = (const float*)d_in[0];
    const float* y       = (const float*)d_in[1];
    const float* conv1_w = (const float*)d_in[2];
    const float* conv1_b = (const float*)d_in[3];
    const float* bn1_g   = (const float*)d_in[4];
    const float* bn1_b   = (const float*)d_in[5];
    const float* conv2_w = (const float*)d_in[6];
    const float* conv2_b = (const float*)d_in[7];
    const float* bn2_g   = (const float*)d_in[8];
    const float* bn2_b   = (const float*)d_in[9];
    const float* fc1_w   = (const float*)d_in[10];
    const float* fc1_b   = (const float*)d_in[11];
    const float* W_rls   = (const float*)d_in[12];
    const int*   sep     = (const int*)d_in[14];
    float* out = (float*)d_out;

    cudaFuncSetAttribute(k_conv2, cudaFuncAttributeMaxDynamicSharedMemorySize, 106624);
    cudaFuncSetAttribute(k_chol, cudaFuncAttributeMaxDynamicSharedMemorySize, 144480);

    float* p1; cudaGetSymbolAddress((void**)&p1, g_part1);
    float* p2; cudaGetSymbolAddress((void**)&p2, g_part2);
    float* b1; cudaGetSymbolAddress((void**)&b1, g_bn1);
    float* b2; cudaGetSymbolAddress((void**)&b2, g_bn2);

    k_conv1_mmx<<<NB, 224>>>(x, conv1_w, conv1_b);
    k_bnfinal<<<32, 256>>>(bn1_g, bn1_b, p1, b1, 32, 1.f / (float)(NB * 784));
    k_conv2<<<NB, 448, 106624>>>(conv2_w, conv2_b);
    k_bnfinal<<<64, 256>>>(bn2_g, bn2_b, p2, b2, 64, 1.f / (float)(NB * 196));
    k_fc1<<<dim3(64, 8), 256>>>(fc1_w);
    k_fc1combine<<<(NB * 128) / 256, 256>>>(fc1_b);
    k_syrk<<<dim3(5, 5, 64), 256>>>();
    k_reduceA<<<66, 256>>>();
    k_phity<<<64, 256>>>(y);
    k_Bfinal<<<6, 256>>>(W_rls);
    k_chol<<<1, 256, 144480>>>(W_rls, sep);
    k_head<<<(NB * 10 + 255) / 256, 256>>>(out);
}